// round 1
// baseline (speedup 1.0000x reference)
#include <cuda_runtime.h>
#include <cstdint>

// ---------------------------------------------------------------------------
// Window-based self-attention (Swin-style), B=64, 56x56, C=128, WS=7, NH=8.
// Round 0: correct fp32 baseline.
//   K1: LayerNorm + window partition  -> g_xw  [200704, 128]  (windowed token order)
//   K2: QKV GEMM (+bias, head-scatter)-> g_qkv [3][4096*8, 49, 16]
//   K3: per-(window,head) attention   -> g_xw  (reused) [200704, 128]
//   K4: out-proj GEMM (+bias, window merge) -> d_out [64,56,56,128]
// ---------------------------------------------------------------------------

#define NTOK      200704            // 4096 windows * 49 tokens
#define CDIM      128
#define QKV_STRIDE 25690112         // NTOK * CDIM
#define SCALE_ATT 0.25f             // HD^-0.5, HD=16
#define LN_EPS    1e-5f

__device__ float g_xw[(size_t)NTOK * CDIM];          // ~102.8 MB (reused for attn out)
__device__ float g_qkv[(size_t)3 * NTOK * CDIM];     // ~308 MB

// ---------------------------------------------------------------------------
// K1: LayerNorm + window partition. One warp per token; lane holds float4.
// ---------------------------------------------------------------------------
__global__ void ln_partition_kernel(const float* __restrict__ x,
                                    const float* __restrict__ gamma,
                                    const float* __restrict__ beta,
                                    float* __restrict__ xw)
{
    const int t    = blockIdx.x * 8 + (threadIdx.x >> 5);   // windowed token index
    const int lane = threadIdx.x & 31;

    const int g = t / 49, p = t - g * 49;
    const int b = g >> 6, w = g & 63;
    const int row = (w >> 3) * 7 + p / 7;
    const int col = (w & 7) * 7 + p % 7;

    const size_t src4 = ((size_t)b * 3136 + row * 56 + col) * 32 + lane; // float4 units
    float4 v = reinterpret_cast<const float4*>(x)[src4];

    float sum = v.x + v.y + v.z + v.w;
    #pragma unroll
    for (int o = 16; o > 0; o >>= 1) sum += __shfl_xor_sync(0xffffffffu, sum, o);
    const float mu = sum * (1.0f / 128.0f);

    float4 d;
    d.x = v.x - mu; d.y = v.y - mu; d.z = v.z - mu; d.w = v.w - mu;
    float sq = d.x * d.x + d.y * d.y + d.z * d.z + d.w * d.w;
    #pragma unroll
    for (int o = 16; o > 0; o >>= 1) sq += __shfl_xor_sync(0xffffffffu, sq, o);
    const float rstd = rsqrtf(sq * (1.0f / 128.0f) + LN_EPS);

    float4 gm = reinterpret_cast<const float4*>(gamma)[lane];
    float4 bt = reinterpret_cast<const float4*>(beta)[lane];
    float4 o;
    o.x = d.x * rstd * gm.x + bt.x;
    o.y = d.y * rstd * gm.y + bt.y;
    o.z = d.z * rstd * gm.z + bt.z;
    o.w = d.w * rstd * gm.w + bt.w;

    reinterpret_cast<float4*>(xw)[(size_t)t * 32 + lane] = o;
}

// ---------------------------------------------------------------------------
// K2/K4: 128x128-tile fp32 GEMM, K=128 fully resident in smem, 8x8 microtile.
// MODE 0: QKV epilogue  (N=384, scatter q/k/v into [wh][p][d] head layout)
// MODE 1: proj epilogue (N=128, +bias, window-merge scatter into d_out)
// ---------------------------------------------------------------------------
template <int MODE>
__global__ void gemm_tile_kernel(const float* __restrict__ A,
                                 const float* __restrict__ W,
                                 const float* __restrict__ bias,
                                 float* __restrict__ out,
                                 int ldw)
{
    extern __shared__ float sm[];
    float* As = sm;              // [128][128]  row-major (m, k)
    float* Bs = sm + 128 * 128;  // [128][128]  row-major (k, n)

    const int tid = threadIdx.x;
    const int tx = tid & 15;     // col group
    const int ty = tid >> 4;     // row group
    const int mBase = blockIdx.x * 128;
    const int nBase = blockIdx.y * 128;

    // Load A tile: coalesced float4 along k.
    const float4* A4 = reinterpret_cast<const float4*>(A);
    #pragma unroll
    for (int i = tid; i < 4096; i += 256) {
        int m = i >> 5, k4 = i & 31;
        reinterpret_cast<float4*>(As)[i] = A4[(size_t)(mBase + m) * 32 + k4];
    }
    // Load B tile: coalesced float4 along n.
    #pragma unroll
    for (int i = tid; i < 4096; i += 256) {
        int k = i >> 5, n4 = i & 31;
        reinterpret_cast<float4*>(Bs)[i] =
            reinterpret_cast<const float4*>(W + (size_t)k * ldw + nBase)[n4];
    }
    __syncthreads();

    float acc[8][8];
    #pragma unroll
    for (int i = 0; i < 8; i++)
        #pragma unroll
        for (int j = 0; j < 8; j++) acc[i][j] = 0.0f;

    #pragma unroll 4
    for (int k = 0; k < 128; k++) {
        float a[8];
        #pragma unroll
        for (int i = 0; i < 8; i++) a[i] = As[(ty * 8 + i) * 128 + k];
        float4 b0 = *reinterpret_cast<float4*>(&Bs[k * 128 + tx * 8]);
        float4 b1 = *reinterpret_cast<float4*>(&Bs[k * 128 + tx * 8 + 4]);
        float bfr[8] = {b0.x, b0.y, b0.z, b0.w, b1.x, b1.y, b1.z, b1.w};
        #pragma unroll
        for (int i = 0; i < 8; i++)
            #pragma unroll
            for (int j = 0; j < 8; j++)
                acc[i][j] = fmaf(a[i], bfr[j], acc[i][j]);
    }

    // Epilogue
    #pragma unroll
    for (int i = 0; i < 8; i++) {
        const int t = mBase + ty * 8 + i;
        const int g = t / 49, p = t - g * 49;
        if (MODE == 0) {
            #pragma unroll
            for (int j = 0; j < 8; j++) {
                const int jj = nBase + tx * 8 + j;       // 0..383
                const int which = jj >> 7;               // 0=q 1=k 2=v
                const int c = jj & 127;
                const int h = c >> 4, d = c & 15;
                out[(size_t)which * QKV_STRIDE +
                    ((size_t)((g * 8 + h) * 49 + p)) * 16 + d] = acc[i][j] + bias[jj];
            }
        } else {
            const int b = g >> 6, w = g & 63;
            const int row = (w >> 3) * 7 + p / 7;
            const int col = (w & 7) * 7 + p % 7;
            float* op = out + ((size_t)b * 3136 + row * 56 + col) * 128 + nBase + tx * 8;
            const float* bp = bias + nBase + tx * 8;
            #pragma unroll
            for (int j = 0; j < 8; j++) op[j] = acc[i][j] + bp[j];
        }
    }
}

// ---------------------------------------------------------------------------
// K3: attention per (window, head). 49x49 scores, softmax, 49x16 output.
// ---------------------------------------------------------------------------
__global__ void attn_kernel(const float* __restrict__ qkv,
                            float* __restrict__ attnOut)
{
    __shared__ float qs[49 * 16];
    __shared__ float ks[49 * 16];
    __shared__ float vs[49 * 16];
    __shared__ float sc[49 * 49];

    const int wh = blockIdx.x;                 // window*8 + head, 0..32767
    const float* qp = qkv + (size_t)wh * 784;
    const float* kp = qp + QKV_STRIDE;
    const float* vp = qp + 2 * (size_t)QKV_STRIDE;

    for (int i = threadIdx.x; i < 196; i += 128) {
        reinterpret_cast<float4*>(qs)[i] = reinterpret_cast<const float4*>(qp)[i];
        reinterpret_cast<float4*>(ks)[i] = reinterpret_cast<const float4*>(kp)[i];
        reinterpret_cast<float4*>(vs)[i] = reinterpret_cast<const float4*>(vp)[i];
    }
    __syncthreads();

    for (int i = threadIdx.x; i < 2401; i += 128) {
        const int r = i / 49, c = i - r * 49;
        float acc = 0.0f;
        #pragma unroll
        for (int d = 0; d < 16; d++) acc = fmaf(qs[r * 16 + d], ks[c * 16 + d], acc);
        sc[i] = acc * SCALE_ATT;
    }
    __syncthreads();

    // softmax: warp per row
    const int warp = threadIdx.x >> 5, lane = threadIdx.x & 31;
    for (int r = warp; r < 49; r += 4) {
        float v0 = sc[r * 49 + lane];                               // lane 0..31 always valid
        float v1 = (lane + 32 < 49) ? sc[r * 49 + lane + 32] : -1e30f;
        float m = fmaxf(v0, v1);
        #pragma unroll
        for (int o = 16; o > 0; o >>= 1) m = fmaxf(m, __shfl_xor_sync(0xffffffffu, m, o));
        float e0 = expf(v0 - m);
        float e1 = (lane + 32 < 49) ? expf(v1 - m) : 0.0f;
        float s = e0 + e1;
        #pragma unroll
        for (int o = 16; o > 0; o >>= 1) s += __shfl_xor_sync(0xffffffffu, s, o);
        const float inv = 1.0f / s;
        sc[r * 49 + lane] = e0 * inv;
        if (lane + 32 < 49) sc[r * 49 + lane + 32] = e1 * inv;
    }
    __syncthreads();

    const int g = wh >> 3, h = wh & 7;
    for (int i = threadIdx.x; i < 784; i += 128) {
        const int r = i >> 4, d = i & 15;
        float acc = 0.0f;
        #pragma unroll
        for (int c = 0; c < 49; c++) acc = fmaf(sc[r * 49 + c], vs[c * 16 + d], acc);
        attnOut[((size_t)(g * 49 + r)) * 128 + h * 16 + d] = acc;
    }
}

// ---------------------------------------------------------------------------
// Launch
// ---------------------------------------------------------------------------
extern "C" void kernel_launch(void* const* d_in, const int* in_sizes, int n_in,
                              void* d_out, int out_size)
{
    const float* x       = (const float*)d_in[0];
    const float* ln_g    = (const float*)d_in[1];
    const float* ln_b    = (const float*)d_in[2];
    const float* w_qkv   = (const float*)d_in[3];
    const float* b_qkv   = (const float*)d_in[4];
    const float* w_out   = (const float*)d_in[5];
    const float* b_out   = (const float*)d_in[6];
    float* out           = (float*)d_out;

    void *xw_ptr = nullptr, *qkv_ptr = nullptr;
    cudaGetSymbolAddress(&xw_ptr, g_xw);
    cudaGetSymbolAddress(&qkv_ptr, g_qkv);
    float* xw  = (float*)xw_ptr;
    float* qkv = (float*)qkv_ptr;

    const int smem = 2 * 128 * 128 * sizeof(float); // 131072
    cudaFuncSetAttribute((const void*)gemm_tile_kernel<0>,
                         cudaFuncAttributeMaxDynamicSharedMemorySize, smem);
    cudaFuncSetAttribute((const void*)gemm_tile_kernel<1>,
                         cudaFuncAttributeMaxDynamicSharedMemorySize, smem);

    // K1: LN + window partition
    ln_partition_kernel<<<NTOK / 8, 256>>>(x, ln_g, ln_b, xw);

    // K2: QKV GEMM  (M=200704, N=384, K=128)
    gemm_tile_kernel<0><<<dim3(NTOK / 128, 3), 256, smem>>>(xw, w_qkv, b_qkv, qkv, 384);

    // K3: attention (4096 windows * 8 heads), writes back into xw
    attn_kernel<<<32768, 128>>>(qkv, xw);

    // K4: out projection + window merge (M=200704, N=128, K=128)
    gemm_tile_kernel<1><<<dim3(NTOK / 128, 1), 256, smem>>>(xw, w_out, b_out, out, 128);
}

// round 2
// speedup vs baseline: 1.3335x; 1.3335x over previous
#include <cuda_runtime.h>
#include <cstdint>

// ---------------------------------------------------------------------------
// Window-based self-attention (Swin-style), B=64, 56x56, C=128, WS=7, NH=8.
// Round 2: attention kernel rewritten (division-free, register-cached q,
// broadcast-friendly smem access, SMSP-balanced lane mapping, __expf).
//   K1: LayerNorm + window partition  -> g_xw  [200704, 128]
//   K2: QKV GEMM (+bias, head-scatter)-> g_qkv [3][4096*8, 49, 16]
//   K3: per-(window,head) attention   -> g_xw  (reused)
//   K4: out-proj GEMM (+bias, window merge) -> d_out
// ---------------------------------------------------------------------------

#define NTOK      200704            // 4096 windows * 49 tokens
#define CDIM      128
#define QKV_STRIDE 25690112         // NTOK * CDIM
#define SCALE_ATT 0.25f             // HD^-0.5, HD=16
#define LN_EPS    1e-5f

__device__ float g_xw[(size_t)NTOK * CDIM];          // ~102.8 MB (reused for attn out)
__device__ float g_qkv[(size_t)3 * NTOK * CDIM];     // ~308 MB

// ---------------------------------------------------------------------------
// K1: LayerNorm + window partition. One warp per token; lane holds float4.
// ---------------------------------------------------------------------------
__global__ void ln_partition_kernel(const float* __restrict__ x,
                                    const float* __restrict__ gamma,
                                    const float* __restrict__ beta,
                                    float* __restrict__ xw)
{
    const int t    = blockIdx.x * 8 + (threadIdx.x >> 5);   // windowed token index
    const int lane = threadIdx.x & 31;

    const int g = t / 49, p = t - g * 49;
    const int b = g >> 6, w = g & 63;
    const int row = (w >> 3) * 7 + p / 7;
    const int col = (w & 7) * 7 + p % 7;

    const size_t src4 = ((size_t)b * 3136 + row * 56 + col) * 32 + lane; // float4 units
    float4 v = reinterpret_cast<const float4*>(x)[src4];

    float sum = v.x + v.y + v.z + v.w;
    #pragma unroll
    for (int o = 16; o > 0; o >>= 1) sum += __shfl_xor_sync(0xffffffffu, sum, o);
    const float mu = sum * (1.0f / 128.0f);

    float4 d;
    d.x = v.x - mu; d.y = v.y - mu; d.z = v.z - mu; d.w = v.w - mu;
    float sq = d.x * d.x + d.y * d.y + d.z * d.z + d.w * d.w;
    #pragma unroll
    for (int o = 16; o > 0; o >>= 1) sq += __shfl_xor_sync(0xffffffffu, sq, o);
    const float rstd = rsqrtf(sq * (1.0f / 128.0f) + LN_EPS);

    float4 gm = reinterpret_cast<const float4*>(gamma)[lane];
    float4 bt = reinterpret_cast<const float4*>(beta)[lane];
    float4 o;
    o.x = d.x * rstd * gm.x + bt.x;
    o.y = d.y * rstd * gm.y + bt.y;
    o.z = d.z * rstd * gm.z + bt.z;
    o.w = d.w * rstd * gm.w + bt.w;

    reinterpret_cast<float4*>(xw)[(size_t)t * 32 + lane] = o;
}

// ---------------------------------------------------------------------------
// K2/K4: 128x128-tile fp32 GEMM, K=128 fully resident in smem, 8x8 microtile.
// MODE 0: QKV epilogue  (N=384, scatter q/k/v into [wh][p][d] head layout)
// MODE 1: proj epilogue (N=128, +bias, window-merge scatter into d_out)
// ---------------------------------------------------------------------------
template <int MODE>
__global__ void gemm_tile_kernel(const float* __restrict__ A,
                                 const float* __restrict__ W,
                                 const float* __restrict__ bias,
                                 float* __restrict__ out,
                                 int ldw)
{
    extern __shared__ float sm[];
    float* As = sm;              // [128][128]  row-major (m, k)
    float* Bs = sm + 128 * 128;  // [128][128]  row-major (k, n)

    const int tid = threadIdx.x;
    const int tx = tid & 15;     // col group
    const int ty = tid >> 4;     // row group
    const int mBase = blockIdx.x * 128;
    const int nBase = blockIdx.y * 128;

    const float4* A4 = reinterpret_cast<const float4*>(A);
    #pragma unroll
    for (int i = tid; i < 4096; i += 256) {
        int m = i >> 5, k4 = i & 31;
        reinterpret_cast<float4*>(As)[i] = A4[(size_t)(mBase + m) * 32 + k4];
    }
    #pragma unroll
    for (int i = tid; i < 4096; i += 256) {
        int k = i >> 5, n4 = i & 31;
        reinterpret_cast<float4*>(Bs)[i] =
            reinterpret_cast<const float4*>(W + (size_t)k * ldw + nBase)[n4];
    }
    __syncthreads();

    float acc[8][8];
    #pragma unroll
    for (int i = 0; i < 8; i++)
        #pragma unroll
        for (int j = 0; j < 8; j++) acc[i][j] = 0.0f;

    #pragma unroll 4
    for (int k = 0; k < 128; k++) {
        float a[8];
        #pragma unroll
        for (int i = 0; i < 8; i++) a[i] = As[(ty * 8 + i) * 128 + k];
        float4 b0 = *reinterpret_cast<float4*>(&Bs[k * 128 + tx * 8]);
        float4 b1 = *reinterpret_cast<float4*>(&Bs[k * 128 + tx * 8 + 4]);
        float bfr[8] = {b0.x, b0.y, b0.z, b0.w, b1.x, b1.y, b1.z, b1.w};
        #pragma unroll
        for (int i = 0; i < 8; i++)
            #pragma unroll
            for (int j = 0; j < 8; j++)
                acc[i][j] = fmaf(a[i], bfr[j], acc[i][j]);
    }

    #pragma unroll
    for (int i = 0; i < 8; i++) {
        const int t = mBase + ty * 8 + i;
        const int g = t / 49, p = t - g * 49;
        if (MODE == 0) {
            #pragma unroll
            for (int j = 0; j < 8; j++) {
                const int jj = nBase + tx * 8 + j;       // 0..383
                const int which = jj >> 7;               // 0=q 1=k 2=v
                const int c = jj & 127;
                const int h = c >> 4, d = c & 15;
                out[(size_t)which * QKV_STRIDE +
                    ((size_t)((g * 8 + h) * 49 + p)) * 16 + d] = acc[i][j] + bias[jj];
            }
        } else {
            const int b = g >> 6, w = g & 63;
            const int row = (w >> 3) * 7 + p / 7;
            const int col = (w & 7) * 7 + p % 7;
            float* op = out + ((size_t)b * 3136 + row * 56 + col) * 128 + nBase + tx * 8;
            const float* bp = bias + nBase + tx * 8;
            #pragma unroll
            for (int j = 0; j < 8; j++) op[j] = acc[i][j] + bp[j];
        }
    }
}

// ---------------------------------------------------------------------------
// K3: attention per (window, head). Rewritten:
//  - scores: thread=(row r, col-half), q row cached in regs (scale folded in),
//    k rows loaded as broadcast LDS.128; division-free.
//  - softmax: warp per row, __expf.
//  - PV: thread=(row r, d-half), 8 reg accumulators, sc reads conflict-free
//    (stride 49 odd), v rows broadcast.
//  - Work slots mapped as wid*25+lane (lane<25) so active lanes are balanced
//    across all 4 SMSPs.
// ---------------------------------------------------------------------------
__global__ void attn_kernel(const float* __restrict__ qkv,
                            float* __restrict__ attnOut)
{
    __shared__ float qs[49 * 16];
    __shared__ float ks[49 * 16];
    __shared__ float vs[49 * 16];
    __shared__ float sc[49 * 49];

    const int wh  = blockIdx.x;                // window*8 + head
    const int tid = threadIdx.x;
    const int wid = tid >> 5, lane = tid & 31;
    const int slot = wid * 25 + lane;          // valid when lane<25 && slot<98
    const bool active = (lane < 25) && (slot < 98);

    const float* qp = qkv + (size_t)wh * 784;
    const float* kp = qp + QKV_STRIDE;
    const float* vp = qp + 2 * (size_t)QKV_STRIDE;

    for (int i = tid; i < 196; i += 128) {
        reinterpret_cast<float4*>(qs)[i] = reinterpret_cast<const float4*>(qp)[i];
        reinterpret_cast<float4*>(ks)[i] = reinterpret_cast<const float4*>(kp)[i];
        reinterpret_cast<float4*>(vs)[i] = reinterpret_cast<const float4*>(vp)[i];
    }
    __syncthreads();

    // ---- scores: S[r][c] = (q_r . k_c) * SCALE ----
    if (active) {
        const int r    = slot >> 1;
        const int half = slot & 1;
        const int c0   = half * 24;            // half0: c 0..24, half1: c 24..48 (c=24 dup, same value)

        float qr[16];
        {
            const float4* q4 = reinterpret_cast<const float4*>(&qs[r * 16]);
            #pragma unroll
            for (int t4 = 0; t4 < 4; t4++) {
                float4 qv = q4[t4];
                qr[t4 * 4 + 0] = qv.x * SCALE_ATT;
                qr[t4 * 4 + 1] = qv.y * SCALE_ATT;
                qr[t4 * 4 + 2] = qv.z * SCALE_ATT;
                qr[t4 * 4 + 3] = qv.w * SCALE_ATT;
            }
        }
        float* srow = &sc[r * 49];
        #pragma unroll 5
        for (int cc = 0; cc < 25; cc++) {
            const int c = c0 + cc;
            const float4* k4 = reinterpret_cast<const float4*>(&ks[c * 16]);
            float4 k0 = k4[0], k1 = k4[1], k2 = k4[2], k3 = k4[3];
            float acc;
            acc = qr[0]  * k0.x;
            acc = fmaf(qr[1],  k0.y, acc);
            acc = fmaf(qr[2],  k0.z, acc);
            acc = fmaf(qr[3],  k0.w, acc);
            acc = fmaf(qr[4],  k1.x, acc);
            acc = fmaf(qr[5],  k1.y, acc);
            acc = fmaf(qr[6],  k1.z, acc);
            acc = fmaf(qr[7],  k1.w, acc);
            acc = fmaf(qr[8],  k2.x, acc);
            acc = fmaf(qr[9],  k2.y, acc);
            acc = fmaf(qr[10], k2.z, acc);
            acc = fmaf(qr[11], k2.w, acc);
            acc = fmaf(qr[12], k3.x, acc);
            acc = fmaf(qr[13], k3.y, acc);
            acc = fmaf(qr[14], k3.z, acc);
            acc = fmaf(qr[15], k3.w, acc);
            srow[c] = acc;
        }
    }
    __syncthreads();

    // ---- softmax: warp per row ----
    for (int r = wid; r < 49; r += 4) {
        float v0 = sc[r * 49 + lane];
        float v1 = (lane + 32 < 49) ? sc[r * 49 + lane + 32] : -1e30f;
        float m = fmaxf(v0, v1);
        #pragma unroll
        for (int o = 16; o > 0; o >>= 1) m = fmaxf(m, __shfl_xor_sync(0xffffffffu, m, o));
        float e0 = __expf(v0 - m);
        float e1 = (lane + 32 < 49) ? __expf(v1 - m) : 0.0f;
        float s = e0 + e1;
        #pragma unroll
        for (int o = 16; o > 0; o >>= 1) s += __shfl_xor_sync(0xffffffffu, s, o);
        const float inv = 1.0f / s;
        sc[r * 49 + lane] = e0 * inv;
        if (lane + 32 < 49) sc[r * 49 + lane + 32] = e1 * inv;
    }
    __syncthreads();

    // ---- PV: out[r][d] = sum_c P[r][c] * V[c][d] ----
    if (active) {
        const int r  = slot >> 1;
        const int dh = (slot & 1) * 8;

        float acc[8];
        #pragma unroll
        for (int j = 0; j < 8; j++) acc[j] = 0.0f;

        const float* srow = &sc[r * 49];
        #pragma unroll 7
        for (int c = 0; c < 49; c++) {
            const float p = srow[c];
            const float4* v4 = reinterpret_cast<const float4*>(&vs[c * 16 + dh]);
            float4 a = v4[0], b = v4[1];
            acc[0] = fmaf(p, a.x, acc[0]);
            acc[1] = fmaf(p, a.y, acc[1]);
            acc[2] = fmaf(p, a.z, acc[2]);
            acc[3] = fmaf(p, a.w, acc[3]);
            acc[4] = fmaf(p, b.x, acc[4]);
            acc[5] = fmaf(p, b.y, acc[5]);
            acc[6] = fmaf(p, b.z, acc[6]);
            acc[7] = fmaf(p, b.w, acc[7]);
        }

        const int g = wh >> 3, h = wh & 7;
        float* op = attnOut + ((size_t)(g * 49 + r)) * 128 + h * 16 + dh;
        reinterpret_cast<float4*>(op)[0] = make_float4(acc[0], acc[1], acc[2], acc[3]);
        reinterpret_cast<float4*>(op)[1] = make_float4(acc[4], acc[5], acc[6], acc[7]);
    }
}

// ---------------------------------------------------------------------------
// Launch
// ---------------------------------------------------------------------------
extern "C" void kernel_launch(void* const* d_in, const int* in_sizes, int n_in,
                              void* d_out, int out_size)
{
    const float* x       = (const float*)d_in[0];
    const float* ln_g    = (const float*)d_in[1];
    const float* ln_b    = (const float*)d_in[2];
    const float* w_qkv   = (const float*)d_in[3];
    const float* b_qkv   = (const float*)d_in[4];
    const float* w_out   = (const float*)d_in[5];
    const float* b_out   = (const float*)d_in[6];
    float* out           = (float*)d_out;

    void *xw_ptr = nullptr, *qkv_ptr = nullptr;
    cudaGetSymbolAddress(&xw_ptr, g_xw);
    cudaGetSymbolAddress(&qkv_ptr, g_qkv);
    float* xw  = (float*)xw_ptr;
    float* qkv = (float*)qkv_ptr;

    const int smem = 2 * 128 * 128 * sizeof(float); // 131072
    cudaFuncSetAttribute((const void*)gemm_tile_kernel<0>,
                         cudaFuncAttributeMaxDynamicSharedMemorySize, smem);
    cudaFuncSetAttribute((const void*)gemm_tile_kernel<1>,
                         cudaFuncAttributeMaxDynamicSharedMemorySize, smem);

    // K1: LN + window partition
    ln_partition_kernel<<<NTOK / 8, 256>>>(x, ln_g, ln_b, xw);

    // K2: QKV GEMM  (M=200704, N=384, K=128)
    gemm_tile_kernel<0><<<dim3(NTOK / 128, 3), 256, smem>>>(xw, w_qkv, b_qkv, qkv, 384);

    // K3: attention (4096 windows * 8 heads), writes back into xw
    attn_kernel<<<32768, 128>>>(qkv, xw);

    // K4: out projection + window merge (M=200704, N=128, K=128)
    gemm_tile_kernel<1><<<dim3(NTOK / 128, 1), 256, smem>>>(xw, w_out, b_out, out, 128);
}

// round 4
// speedup vs baseline: 1.7515x; 1.3134x over previous
#include <cuda_runtime.h>
#include <cstdint>

// ---------------------------------------------------------------------------
// Window-based self-attention (Swin-style), B=64, 56x56, C=128, WS=7, NH=8.
// Round 4: K2/K4 GEMMs on tensor pipe via mma.sync tf32 (arch-generic PTX;
// tcgen05 is rejected by the harness's .target sm_103 PTX stage).
//   K0: transpose weights -> g_wT
//   K1: LayerNorm + window partition  -> g_xw  [200704, 128]
//   K2: QKV GEMM tf32 mma (+bias, head-scatter) -> g_qkv  (A-tile reused x3)
//   K3: per-(window,head) attention fp32 -> g_xw (reused)
//   K4: out-proj GEMM tf32 mma (+bias, window merge) -> d_out
// ---------------------------------------------------------------------------

#define NTOK      200704            // 4096 windows * 49 tokens
#define CDIM      128
#define QKV_STRIDE 25690112         // NTOK * CDIM
#define SCALE_ATT 0.25f             // HD^-0.5, HD=16
#define LN_EPS    1e-5f
#define SMEM_LDA  132               // padded row stride (floats)

__device__ float g_xw[(size_t)NTOK * CDIM];          // ~102.8 MB (reused for attn out)
__device__ float g_qkv[(size_t)3 * NTOK * CDIM];     // ~308 MB
__device__ float g_wT[384 * 128 + 128 * 128];        // transposed w_qkv | w_out

// ---------------------------------------------------------------------------
// helpers
// ---------------------------------------------------------------------------
__device__ __forceinline__ float to_tf32(float x) {
    asm("cvt.rna.tf32.f32 %0, %0;" : "+f"(x));
    return x;
}
__device__ __forceinline__ void mma_tf32(float* c,
                                         uint32_t a0, uint32_t a1, uint32_t a2, uint32_t a3,
                                         uint32_t b0, uint32_t b1) {
    asm volatile(
        "mma.sync.aligned.m16n8k8.row.col.f32.tf32.tf32.f32 "
        "{%0,%1,%2,%3}, {%4,%5,%6,%7}, {%8,%9}, {%0,%1,%2,%3};"
        : "+f"(c[0]), "+f"(c[1]), "+f"(c[2]), "+f"(c[3])
        : "r"(a0), "r"(a1), "r"(a2), "r"(a3), "r"(b0), "r"(b1));
}

// ---------------------------------------------------------------------------
// K0: transpose weights (w_qkv [128,384] -> [384,128]; w_out [128,128] -> T)
// ---------------------------------------------------------------------------
__global__ void transpose_w_kernel(const float* __restrict__ wqkv,
                                   const float* __restrict__ wout,
                                   float* __restrict__ wT)
{
    const int i = blockIdx.x * 256 + threadIdx.x;
    if (i < 49152) {
        const int k = i / 384, n = i - k * 384;
        wT[n * 128 + k] = wqkv[i];
    }
    if (i < 16384) {
        const int k = i >> 7, n = i & 127;
        wT[49152 + n * 128 + k] = wout[i];
    }
}

// ---------------------------------------------------------------------------
// K1: LayerNorm + window partition. One warp per token.
// ---------------------------------------------------------------------------
__global__ void ln_partition_kernel(const float* __restrict__ x,
                                    const float* __restrict__ gamma,
                                    const float* __restrict__ beta,
                                    float* __restrict__ xw)
{
    const int t    = blockIdx.x * 8 + (threadIdx.x >> 5);
    const int lane = threadIdx.x & 31;

    const int g = t / 49, p = t - g * 49;
    const int b = g >> 6, w = g & 63;
    const int row = (w >> 3) * 7 + p / 7;
    const int col = (w & 7) * 7 + p % 7;

    const size_t src4 = ((size_t)b * 3136 + row * 56 + col) * 32 + lane;
    float4 v = reinterpret_cast<const float4*>(x)[src4];

    float sum = v.x + v.y + v.z + v.w;
    #pragma unroll
    for (int o = 16; o > 0; o >>= 1) sum += __shfl_xor_sync(0xffffffffu, sum, o);
    const float mu = sum * (1.0f / 128.0f);

    float4 d;
    d.x = v.x - mu; d.y = v.y - mu; d.z = v.z - mu; d.w = v.w - mu;
    float sq = d.x * d.x + d.y * d.y + d.z * d.z + d.w * d.w;
    #pragma unroll
    for (int o = 16; o > 0; o >>= 1) sq += __shfl_xor_sync(0xffffffffu, sq, o);
    const float rstd = rsqrtf(sq * (1.0f / 128.0f) + LN_EPS);

    float4 gm = reinterpret_cast<const float4*>(gamma)[lane];
    float4 bt = reinterpret_cast<const float4*>(beta)[lane];
    float4 o;
    o.x = d.x * rstd * gm.x + bt.x;
    o.y = d.y * rstd * gm.y + bt.y;
    o.z = d.z * rstd * gm.z + bt.z;
    o.w = d.w * rstd * gm.w + bt.w;

    reinterpret_cast<float4*>(xw)[(size_t)t * 32 + lane] = o;
}

// ---------------------------------------------------------------------------
// K2/K4: tf32 mma.sync GEMM. 128x128 tile, K=128 resident, 8 warps (2x4),
// each warp 64x32 = 16 m16n8k8 tiles, 16 k-steps.
// MODE 0 (NBLK=3): QKV — loop 3 N-blocks reusing the A tile; head-scatter out.
// MODE 1 (NBLK=1): out-proj — +bias, window-merge scatter.
// ---------------------------------------------------------------------------
template <int MODE, int NBLK>
__global__ void __launch_bounds__(256, 1)
gemm_mma_kernel(const float* __restrict__ A,
                const float* __restrict__ WT,      // [N_total, 128] row-major
                const float* __restrict__ bias,
                float* __restrict__ out)
{
    extern __shared__ float sm[];
    float* As = sm;                          // [128][SMEM_LDA]
    float* Bs = sm + 128 * SMEM_LDA;         // [128][SMEM_LDA]

    const int tid  = threadIdx.x;
    const int warp = tid >> 5, lane = tid & 31;
    const int wm = (warp >> 2) * 64;         // warp m offset (0/64)
    const int wn = (warp & 3) * 32;          // warp n offset (0/32/64/96)
    const int qrow = lane >> 2;              // 0..7
    const int qcol = lane & 3;               // 0..3
    const int mBase = blockIdx.x * 128;

    // Fill A tile once: coalesced float4 along k, tf32-round, padded store.
    const float4* A4 = reinterpret_cast<const float4*>(A);
    #pragma unroll
    for (int i = tid; i < 4096; i += 256) {
        const int m = i >> 5, k4 = i & 31;
        float4 v = A4[(size_t)(mBase + m) * 32 + k4];
        v.x = to_tf32(v.x); v.y = to_tf32(v.y);
        v.z = to_tf32(v.z); v.w = to_tf32(v.w);
        *reinterpret_cast<float4*>(&As[m * SMEM_LDA + k4 * 4]) = v;
    }

    const float* aBase = As + (wm + qrow) * SMEM_LDA + qcol;
    const float* bBase = Bs + (wn + qrow) * SMEM_LDA + qcol;
    const float4* W4 = reinterpret_cast<const float4*>(WT);

    for (int y = 0; y < NBLK; y++) {
        const int nBase = y * 128;

        // Fill B tile for this N-block (WT rows nBase..nBase+127).
        #pragma unroll
        for (int i = tid; i < 4096; i += 256) {
            const int n = i >> 5, k4 = i & 31;
            float4 v = W4[(size_t)(nBase + n) * 32 + k4];
            v.x = to_tf32(v.x); v.y = to_tf32(v.y);
            v.z = to_tf32(v.z); v.w = to_tf32(v.w);
            *reinterpret_cast<float4*>(&Bs[n * SMEM_LDA + k4 * 4]) = v;
        }
        __syncthreads();

        float acc[4][4][4];
        #pragma unroll
        for (int i = 0; i < 4; i++)
            #pragma unroll
            for (int j = 0; j < 4; j++)
                #pragma unroll
                for (int r = 0; r < 4; r++) acc[i][j][r] = 0.0f;

        #pragma unroll
        for (int ks = 0; ks < 16; ks++) {
            const int kk = ks * 8;
            uint32_t af[4][4];
            #pragma unroll
            for (int i = 0; i < 4; i++) {
                const float* ap = aBase + i * 16 * SMEM_LDA + kk;
                af[i][0] = __float_as_uint(ap[0]);
                af[i][1] = __float_as_uint(ap[8 * SMEM_LDA]);
                af[i][2] = __float_as_uint(ap[4]);
                af[i][3] = __float_as_uint(ap[8 * SMEM_LDA + 4]);
            }
            uint32_t bf[4][2];
            #pragma unroll
            for (int j = 0; j < 4; j++) {
                const float* bp = bBase + j * 8 * SMEM_LDA + kk;
                bf[j][0] = __float_as_uint(bp[0]);
                bf[j][1] = __float_as_uint(bp[4]);
            }
            #pragma unroll
            for (int i = 0; i < 4; i++)
                #pragma unroll
                for (int j = 0; j < 4; j++)
                    mma_tf32(acc[i][j], af[i][0], af[i][1], af[i][2], af[i][3],
                             bf[j][0], bf[j][1]);
        }

        // Epilogue. c0: (row, 2*qcol) c1: +1col  c2: (row+8, 2*qcol) c3: +1col
        #pragma unroll
        for (int i = 0; i < 4; i++) {
            #pragma unroll
            for (int half = 0; half < 2; half++) {
                const int t = mBase + wm + i * 16 + qrow + half * 8;
                const int g = t / 49, p = t - g * 49;
                if (MODE == 0) {
                    #pragma unroll
                    for (int j = 0; j < 4; j++) {
                        const int jj = nBase + wn + j * 8 + 2 * qcol;
                        const int which = jj >> 7;
                        const int ch = jj & 127;
                        const int h = ch >> 4, d = ch & 15;
                        float2 v;
                        v.x = acc[i][j][half * 2 + 0] + __ldg(&bias[jj]);
                        v.y = acc[i][j][half * 2 + 1] + __ldg(&bias[jj + 1]);
                        *reinterpret_cast<float2*>(
                            out + (size_t)which * QKV_STRIDE +
                            ((size_t)((g * 8 + h) * 49 + p)) * 16 + d) = v;
                    }
                } else {
                    const int b = g >> 6, w = g & 63;
                    const int row = (w >> 3) * 7 + p / 7;
                    const int col = (w & 7) * 7 + p % 7;
                    float* op = out + ((size_t)b * 3136 + row * 56 + col) * 128;
                    #pragma unroll
                    for (int j = 0; j < 4; j++) {
                        const int cofs = wn + j * 8 + 2 * qcol;
                        float2 v;
                        v.x = acc[i][j][half * 2 + 0] + __ldg(&bias[cofs]);
                        v.y = acc[i][j][half * 2 + 1] + __ldg(&bias[cofs + 1]);
                        *reinterpret_cast<float2*>(op + cofs) = v;
                    }
                }
            }
        }
        __syncthreads();   // Bs reads done before next fill
    }
}

// ---------------------------------------------------------------------------
// K3: attention per (window, head) — fp32, SMSP-balanced (unchanged from R2).
// ---------------------------------------------------------------------------
__global__ void attn_kernel(const float* __restrict__ qkv,
                            float* __restrict__ attnOut)
{
    __shared__ float qs[49 * 16];
    __shared__ float ks[49 * 16];
    __shared__ float vs[49 * 16];
    __shared__ float sc[49 * 49];

    const int wh  = blockIdx.x;
    const int tid = threadIdx.x;
    const int wid = tid >> 5, lane = tid & 31;
    const int slot = wid * 25 + lane;
    const bool active = (lane < 25) && (slot < 98);

    const float* qp = qkv + (size_t)wh * 784;
    const float* kp = qp + QKV_STRIDE;
    const float* vp = qp + 2 * (size_t)QKV_STRIDE;

    for (int i = tid; i < 196; i += 128) {
        reinterpret_cast<float4*>(qs)[i] = reinterpret_cast<const float4*>(qp)[i];
        reinterpret_cast<float4*>(ks)[i] = reinterpret_cast<const float4*>(kp)[i];
        reinterpret_cast<float4*>(vs)[i] = reinterpret_cast<const float4*>(vp)[i];
    }
    __syncthreads();

    if (active) {
        const int r    = slot >> 1;
        const int half = slot & 1;
        const int c0   = half * 24;

        float qr[16];
        {
            const float4* q4 = reinterpret_cast<const float4*>(&qs[r * 16]);
            #pragma unroll
            for (int t4 = 0; t4 < 4; t4++) {
                float4 qv = q4[t4];
                qr[t4 * 4 + 0] = qv.x * SCALE_ATT;
                qr[t4 * 4 + 1] = qv.y * SCALE_ATT;
                qr[t4 * 4 + 2] = qv.z * SCALE_ATT;
                qr[t4 * 4 + 3] = qv.w * SCALE_ATT;
            }
        }
        float* srow = &sc[r * 49];
        #pragma unroll 5
        for (int cc = 0; cc < 25; cc++) {
            const int c = c0 + cc;
            const float4* k4 = reinterpret_cast<const float4*>(&ks[c * 16]);
            float4 k0 = k4[0], k1 = k4[1], k2 = k4[2], k3 = k4[3];
            float acc;
            acc = qr[0]  * k0.x;
            acc = fmaf(qr[1],  k0.y, acc);
            acc = fmaf(qr[2],  k0.z, acc);
            acc = fmaf(qr[3],  k0.w, acc);
            acc = fmaf(qr[4],  k1.x, acc);
            acc = fmaf(qr[5],  k1.y, acc);
            acc = fmaf(qr[6],  k1.z, acc);
            acc = fmaf(qr[7],  k1.w, acc);
            acc = fmaf(qr[8],  k2.x, acc);
            acc = fmaf(qr[9],  k2.y, acc);
            acc = fmaf(qr[10], k2.z, acc);
            acc = fmaf(qr[11], k2.w, acc);
            acc = fmaf(qr[12], k3.x, acc);
            acc = fmaf(qr[13], k3.y, acc);
            acc = fmaf(qr[14], k3.z, acc);
            acc = fmaf(qr[15], k3.w, acc);
            srow[c] = acc;
        }
    }
    __syncthreads();

    for (int r = wid; r < 49; r += 4) {
        float v0 = sc[r * 49 + lane];
        float v1 = (lane + 32 < 49) ? sc[r * 49 + lane + 32] : -1e30f;
        float m = fmaxf(v0, v1);
        #pragma unroll
        for (int o = 16; o > 0; o >>= 1) m = fmaxf(m, __shfl_xor_sync(0xffffffffu, m, o));
        float e0 = __expf(v0 - m);
        float e1 = (lane + 32 < 49) ? __expf(v1 - m) : 0.0f;
        float s = e0 + e1;
        #pragma unroll
        for (int o = 16; o > 0; o >>= 1) s += __shfl_xor_sync(0xffffffffu, s, o);
        const float inv = 1.0f / s;
        sc[r * 49 + lane] = e0 * inv;
        if (lane + 32 < 49) sc[r * 49 + lane + 32] = e1 * inv;
    }
    __syncthreads();

    if (active) {
        const int r  = slot >> 1;
        const int dh = (slot & 1) * 8;

        float acc[8];
        #pragma unroll
        for (int j = 0; j < 8; j++) acc[j] = 0.0f;

        const float* srow = &sc[r * 49];
        #pragma unroll 7
        for (int c = 0; c < 49; c++) {
            const float p = srow[c];
            const float4* v4 = reinterpret_cast<const float4*>(&vs[c * 16 + dh]);
            float4 a = v4[0], b = v4[1];
            acc[0] = fmaf(p, a.x, acc[0]);
            acc[1] = fmaf(p, a.y, acc[1]);
            acc[2] = fmaf(p, a.z, acc[2]);
            acc[3] = fmaf(p, a.w, acc[3]);
            acc[4] = fmaf(p, b.x, acc[4]);
            acc[5] = fmaf(p, b.y, acc[5]);
            acc[6] = fmaf(p, b.z, acc[6]);
            acc[7] = fmaf(p, b.w, acc[7]);
        }

        const int g = wh >> 3, h = wh & 7;
        float* op = attnOut + ((size_t)(g * 49 + r)) * 128 + h * 16 + dh;
        reinterpret_cast<float4*>(op)[0] = make_float4(acc[0], acc[1], acc[2], acc[3]);
        reinterpret_cast<float4*>(op)[1] = make_float4(acc[4], acc[5], acc[6], acc[7]);
    }
}

// ---------------------------------------------------------------------------
// Launch
// ---------------------------------------------------------------------------
extern "C" void kernel_launch(void* const* d_in, const int* in_sizes, int n_in,
                              void* d_out, int out_size)
{
    const float* x       = (const float*)d_in[0];
    const float* ln_g    = (const float*)d_in[1];
    const float* ln_b    = (const float*)d_in[2];
    const float* w_qkv   = (const float*)d_in[3];
    const float* b_qkv   = (const float*)d_in[4];
    const float* w_out   = (const float*)d_in[5];
    const float* b_out   = (const float*)d_in[6];
    float* out           = (float*)d_out;

    void *xw_ptr = nullptr, *qkv_ptr = nullptr, *wT_ptr = nullptr;
    cudaGetSymbolAddress(&xw_ptr, g_xw);
    cudaGetSymbolAddress(&qkv_ptr, g_qkv);
    cudaGetSymbolAddress(&wT_ptr, g_wT);
    float* xw  = (float*)xw_ptr;
    float* qkv = (float*)qkv_ptr;
    float* wT  = (float*)wT_ptr;

    const int smem = 2 * 128 * SMEM_LDA * sizeof(float);  // 135168 B
    cudaFuncSetAttribute((const void*)gemm_mma_kernel<0, 3>,
                         cudaFuncAttributeMaxDynamicSharedMemorySize, smem);
    cudaFuncSetAttribute((const void*)gemm_mma_kernel<1, 1>,
                         cudaFuncAttributeMaxDynamicSharedMemorySize, smem);

    // K0: weight transpose (tiny)
    transpose_w_kernel<<<192, 256>>>(w_qkv, w_out, wT);

    // K1: LN + window partition
    ln_partition_kernel<<<NTOK / 8, 256>>>(x, ln_g, ln_b, xw);

    // K2: QKV GEMM tf32 mma  (M=200704, N=384, K=128; A tile reused over 3 N-blocks)
    gemm_mma_kernel<0, 3><<<NTOK / 128, 256, smem>>>(xw, wT, b_qkv, qkv);

    // K3: attention (4096 windows * 8 heads), writes back into xw
    attn_kernel<<<32768, 128>>>(qkv, xw);

    // K4: out projection tf32 mma + window merge
    gemm_mma_kernel<1, 1><<<NTOK / 128, 256, smem>>>(xw, wT + 49152, b_out, out);
}

// round 5
// speedup vs baseline: 2.4057x; 1.3735x over previous
#include <cuda_runtime.h>
#include <cstdint>

// ---------------------------------------------------------------------------
// Window-based self-attention (Swin-style), B=64, 56x56, C=128, WS=7, NH=8.
// Round 5: attention moved to tensor pipe (mma.sync tf32, 3-term split for
// fp32-level accuracy). One warp per (window, head).
//   K0: transpose weights -> g_wT
//   K1: LayerNorm + window partition  -> g_xw
//   K2: QKV GEMM tf32 mma (+bias, head-scatter) -> g_qkv
//   K3: attention via mma (split tf32) -> g_xw (reused)
//   K4: out-proj GEMM tf32 mma (+bias, window merge) -> d_out
// ---------------------------------------------------------------------------

#define NTOK      200704            // 4096 windows * 49 tokens
#define CDIM      128
#define QKV_STRIDE 25690112         // NTOK * CDIM
#define SCALE_ATT 0.25f             // HD^-0.5, HD=16
#define LN_EPS    1e-5f
#define SMEM_LDA  132               // padded row stride (floats) for GEMM

__device__ float g_xw[(size_t)NTOK * CDIM];          // ~102.8 MB (reused for attn out)
__device__ float g_qkv[(size_t)3 * NTOK * CDIM];     // ~308 MB
__device__ float g_wT[384 * 128 + 128 * 128];        // transposed w_qkv | w_out

// ---------------------------------------------------------------------------
// helpers
// ---------------------------------------------------------------------------
__device__ __forceinline__ float to_tf32(float x) {
    asm("cvt.rna.tf32.f32 %0, %0;" : "+f"(x));
    return x;
}
__device__ __forceinline__ void mma_tf32(float* c,
                                         uint32_t a0, uint32_t a1, uint32_t a2, uint32_t a3,
                                         uint32_t b0, uint32_t b1) {
    asm volatile(
        "mma.sync.aligned.m16n8k8.row.col.f32.tf32.tf32.f32 "
        "{%0,%1,%2,%3}, {%4,%5,%6,%7}, {%8,%9}, {%0,%1,%2,%3};"
        : "+f"(c[0]), "+f"(c[1]), "+f"(c[2]), "+f"(c[3])
        : "r"(a0), "r"(a1), "r"(a2), "r"(a3), "r"(b0), "r"(b1));
}

// ---------------------------------------------------------------------------
// K0: transpose weights (w_qkv [128,384] -> [384,128]; w_out [128,128] -> T)
// ---------------------------------------------------------------------------
__global__ void transpose_w_kernel(const float* __restrict__ wqkv,
                                   const float* __restrict__ wout,
                                   float* __restrict__ wT)
{
    const int i = blockIdx.x * 256 + threadIdx.x;
    if (i < 49152) {
        const int k = i / 384, n = i - k * 384;
        wT[n * 128 + k] = wqkv[i];
    }
    if (i < 16384) {
        const int k = i >> 7, n = i & 127;
        wT[49152 + n * 128 + k] = wout[i];
    }
}

// ---------------------------------------------------------------------------
// K1: LayerNorm + window partition. One warp per token.
// ---------------------------------------------------------------------------
__global__ void ln_partition_kernel(const float* __restrict__ x,
                                    const float* __restrict__ gamma,
                                    const float* __restrict__ beta,
                                    float* __restrict__ xw)
{
    const int t    = blockIdx.x * 8 + (threadIdx.x >> 5);
    const int lane = threadIdx.x & 31;

    const int g = t / 49, p = t - g * 49;
    const int b = g >> 6, w = g & 63;
    const int row = (w >> 3) * 7 + p / 7;
    const int col = (w & 7) * 7 + p % 7;

    const size_t src4 = ((size_t)b * 3136 + row * 56 + col) * 32 + lane;
    float4 v = reinterpret_cast<const float4*>(x)[src4];

    float sum = v.x + v.y + v.z + v.w;
    #pragma unroll
    for (int o = 16; o > 0; o >>= 1) sum += __shfl_xor_sync(0xffffffffu, sum, o);
    const float mu = sum * (1.0f / 128.0f);

    float4 d;
    d.x = v.x - mu; d.y = v.y - mu; d.z = v.z - mu; d.w = v.w - mu;
    float sq = d.x * d.x + d.y * d.y + d.z * d.z + d.w * d.w;
    #pragma unroll
    for (int o = 16; o > 0; o >>= 1) sq += __shfl_xor_sync(0xffffffffu, sq, o);
    const float rstd = rsqrtf(sq * (1.0f / 128.0f) + LN_EPS);

    float4 gm = reinterpret_cast<const float4*>(gamma)[lane];
    float4 bt = reinterpret_cast<const float4*>(beta)[lane];
    float4 o;
    o.x = d.x * rstd * gm.x + bt.x;
    o.y = d.y * rstd * gm.y + bt.y;
    o.z = d.z * rstd * gm.z + bt.z;
    o.w = d.w * rstd * gm.w + bt.w;

    reinterpret_cast<float4*>(xw)[(size_t)t * 32 + lane] = o;
}

// ---------------------------------------------------------------------------
// K2/K4: tf32 mma.sync GEMM (unchanged from R4, passing).
// ---------------------------------------------------------------------------
template <int MODE, int NBLK>
__global__ void __launch_bounds__(256, 1)
gemm_mma_kernel(const float* __restrict__ A,
                const float* __restrict__ WT,      // [N_total, 128] row-major
                const float* __restrict__ bias,
                float* __restrict__ out)
{
    extern __shared__ float sm[];
    float* As = sm;                          // [128][SMEM_LDA]
    float* Bs = sm + 128 * SMEM_LDA;         // [128][SMEM_LDA]

    const int tid  = threadIdx.x;
    const int warp = tid >> 5, lane = tid & 31;
    const int wm = (warp >> 2) * 64;
    const int wn = (warp & 3) * 32;
    const int qrow = lane >> 2;
    const int qcol = lane & 3;
    const int mBase = blockIdx.x * 128;

    const float4* A4 = reinterpret_cast<const float4*>(A);
    #pragma unroll
    for (int i = tid; i < 4096; i += 256) {
        const int m = i >> 5, k4 = i & 31;
        float4 v = A4[(size_t)(mBase + m) * 32 + k4];
        v.x = to_tf32(v.x); v.y = to_tf32(v.y);
        v.z = to_tf32(v.z); v.w = to_tf32(v.w);
        *reinterpret_cast<float4*>(&As[m * SMEM_LDA + k4 * 4]) = v;
    }

    const float* aBase = As + (wm + qrow) * SMEM_LDA + qcol;
    const float* bBase = Bs + (wn + qrow) * SMEM_LDA + qcol;
    const float4* W4 = reinterpret_cast<const float4*>(WT);

    for (int y = 0; y < NBLK; y++) {
        const int nBase = y * 128;

        #pragma unroll
        for (int i = tid; i < 4096; i += 256) {
            const int n = i >> 5, k4 = i & 31;
            float4 v = W4[(size_t)(nBase + n) * 32 + k4];
            v.x = to_tf32(v.x); v.y = to_tf32(v.y);
            v.z = to_tf32(v.z); v.w = to_tf32(v.w);
            *reinterpret_cast<float4*>(&Bs[n * SMEM_LDA + k4 * 4]) = v;
        }
        __syncthreads();

        float acc[4][4][4];
        #pragma unroll
        for (int i = 0; i < 4; i++)
            #pragma unroll
            for (int j = 0; j < 4; j++)
                #pragma unroll
                for (int r = 0; r < 4; r++) acc[i][j][r] = 0.0f;

        #pragma unroll
        for (int ks = 0; ks < 16; ks++) {
            const int kk = ks * 8;
            uint32_t af[4][4];
            #pragma unroll
            for (int i = 0; i < 4; i++) {
                const float* ap = aBase + i * 16 * SMEM_LDA + kk;
                af[i][0] = __float_as_uint(ap[0]);
                af[i][1] = __float_as_uint(ap[8 * SMEM_LDA]);
                af[i][2] = __float_as_uint(ap[4]);
                af[i][3] = __float_as_uint(ap[8 * SMEM_LDA + 4]);
            }
            uint32_t bf[4][2];
            #pragma unroll
            for (int j = 0; j < 4; j++) {
                const float* bp = bBase + j * 8 * SMEM_LDA + kk;
                bf[j][0] = __float_as_uint(bp[0]);
                bf[j][1] = __float_as_uint(bp[4]);
            }
            #pragma unroll
            for (int i = 0; i < 4; i++)
                #pragma unroll
                for (int j = 0; j < 4; j++)
                    mma_tf32(acc[i][j], af[i][0], af[i][1], af[i][2], af[i][3],
                             bf[j][0], bf[j][1]);
        }

        #pragma unroll
        for (int i = 0; i < 4; i++) {
            #pragma unroll
            for (int half = 0; half < 2; half++) {
                const int t = mBase + wm + i * 16 + qrow + half * 8;
                const int g = t / 49, p = t - g * 49;
                if (MODE == 0) {
                    #pragma unroll
                    for (int j = 0; j < 4; j++) {
                        const int jj = nBase + wn + j * 8 + 2 * qcol;
                        const int which = jj >> 7;
                        const int ch = jj & 127;
                        const int h = ch >> 4, d = ch & 15;
                        float2 v;
                        v.x = acc[i][j][half * 2 + 0] + __ldg(&bias[jj]);
                        v.y = acc[i][j][half * 2 + 1] + __ldg(&bias[jj + 1]);
                        *reinterpret_cast<float2*>(
                            out + (size_t)which * QKV_STRIDE +
                            ((size_t)((g * 8 + h) * 49 + p)) * 16 + d) = v;
                    }
                } else {
                    const int b = g >> 6, w = g & 63;
                    const int row = (w >> 3) * 7 + p / 7;
                    const int col = (w & 7) * 7 + p % 7;
                    float* op = out + ((size_t)b * 3136 + row * 56 + col) * 128;
                    #pragma unroll
                    for (int j = 0; j < 4; j++) {
                        const int cofs = wn + j * 8 + 2 * qcol;
                        float2 v;
                        v.x = acc[i][j][half * 2 + 0] + __ldg(&bias[cofs]);
                        v.y = acc[i][j][half * 2 + 1] + __ldg(&bias[cofs + 1]);
                        *reinterpret_cast<float2*>(op + cofs) = v;
                    }
                }
            }
        }
        __syncthreads();
    }
}

// ---------------------------------------------------------------------------
// K3: tensor-core attention. One warp per (window, head); 8 warps = 1 window.
// S (49x49, padded 64x56) via 4x7 m16n8k8 tiles x 2 k-steps, split-tf32 (3 mma).
// Softmax in C-fragment layout (quad shfl reductions). C->A transform via
// shuffles, then PV (4x2x7 tiles), split-tf32. 1/rowsum folded into the store.
// Per-warp smem: Q[49][20], K[49][20], Vt[16][60] fp32 (pads -> conflict-free).
// ---------------------------------------------------------------------------
#define ATT_WSLAB 2944   // floats per warp slab (980 + 980 + 960 + pad)

__global__ void __launch_bounds__(256, 1)
attn_mma_kernel(const float* __restrict__ qkv, float* __restrict__ attnOut)
{
    extern __shared__ float smd[];
    const int g    = blockIdx.x;             // window
    const int warp = threadIdx.x >> 5;       // head
    const int lane = threadIdx.x & 31;
    const int qrow = lane >> 2;              // 0..7
    const int qcol = lane & 3;               // 0..3
    const int wh   = g * 8 + warp;

    float* qs  = smd + warp * ATT_WSLAB;     // [49][20]
    float* ks_ = qs + 980;                   // [49][20]
    float* vt  = qs + 1960;                  // [16][60]  (V transposed)

    const float* qp = qkv + (size_t)wh * 784;
    const float* kp = qp + QKV_STRIDE;
    const float* vp = qp + 2 * (size_t)QKV_STRIDE;

    // zero Vt pad cols 49..59 (read by k-tile 6; must be 0 so P*garbage != NaN)
    for (int i = lane; i < 176; i += 32) {
        const int d = i / 11, c = 49 + (i % 11);
        vt[d * 60 + c] = 0.0f;
    }
    // fill Q (scale folded), K, Vt
    for (int idx = lane; idx < 196; idx += 32) {
        const int row = idx >> 2, c4 = (idx & 3) * 4;
        float4 q = reinterpret_cast<const float4*>(qp)[idx];
        q.x *= SCALE_ATT; q.y *= SCALE_ATT; q.z *= SCALE_ATT; q.w *= SCALE_ATT;
        *reinterpret_cast<float4*>(&qs[row * 20 + c4]) = q;
        float4 k = reinterpret_cast<const float4*>(kp)[idx];
        *reinterpret_cast<float4*>(&ks_[row * 20 + c4]) = k;
        float4 v = reinterpret_cast<const float4*>(vp)[idx];
        vt[(c4 + 0) * 60 + row] = v.x;
        vt[(c4 + 1) * 60 + row] = v.y;
        vt[(c4 + 2) * 60 + row] = v.z;
        vt[(c4 + 3) * 60 + row] = v.w;
    }
    __syncwarp();

    // ---- scores: S = Q K^T (split tf32: Ah*Bh + Ah*Bl + Al*Bh) ----
    float sc[4][7][4];
    #pragma unroll
    for (int i = 0; i < 4; i++)
        #pragma unroll
        for (int j = 0; j < 7; j++)
            #pragma unroll
            for (int r = 0; r < 4; r++) sc[i][j][r] = 0.0f;

    #pragma unroll
    for (int ks = 0; ks < 2; ks++) {
        const int kk = ks * 8;
        uint32_t ah[4][4], al[4][4];
        #pragma unroll
        for (int i = 0; i < 4; i++) {
            const float* ap = qs + (i * 16 + qrow) * 20 + kk + qcol;
            float a0 = ap[0], a1 = ap[160], a2 = ap[4], a3 = ap[164];
            float h0 = to_tf32(a0), h1 = to_tf32(a1), h2 = to_tf32(a2), h3 = to_tf32(a3);
            ah[i][0] = __float_as_uint(h0); ah[i][1] = __float_as_uint(h1);
            ah[i][2] = __float_as_uint(h2); ah[i][3] = __float_as_uint(h3);
            al[i][0] = __float_as_uint(a0 - h0); al[i][1] = __float_as_uint(a1 - h1);
            al[i][2] = __float_as_uint(a2 - h2); al[i][3] = __float_as_uint(a3 - h3);
        }
        #pragma unroll
        for (int j = 0; j < 7; j++) {
            const float* bp = ks_ + (j * 8 + qrow) * 20 + kk + qcol;
            float b0 = bp[0], b1 = bp[4];
            float h0 = to_tf32(b0), h1 = to_tf32(b1);
            uint32_t Bh0 = __float_as_uint(h0), Bh1 = __float_as_uint(h1);
            uint32_t Bl0 = __float_as_uint(b0 - h0), Bl1 = __float_as_uint(b1 - h1);
            #pragma unroll
            for (int i = 0; i < 4; i++) {
                mma_tf32(sc[i][j], ah[i][0], ah[i][1], ah[i][2], ah[i][3], Bh0, Bh1);
                mma_tf32(sc[i][j], ah[i][0], ah[i][1], ah[i][2], ah[i][3], Bl0, Bl1);
                mma_tf32(sc[i][j], al[i][0], al[i][1], al[i][2], al[i][3], Bh0, Bh1);
            }
        }
    }

    // ---- softmax in C layout (rows: lo=16i+qrow, hi=+8; cols 8j+2qcol+{0,1}) ----
    float invlo[4], invhi[4];
    #pragma unroll
    for (int i = 0; i < 4; i++) {
        // mask invalid cols (tile j=6 covers cols 48..55; only col 48 valid)
        if (qcol != 0) { sc[i][6][0] = -1e30f; sc[i][6][2] = -1e30f; }
        sc[i][6][1] = -1e30f; sc[i][6][3] = -1e30f;

        float mlo = -1e30f, mhi = -1e30f;
        #pragma unroll
        for (int j = 0; j < 7; j++) {
            mlo = fmaxf(mlo, fmaxf(sc[i][j][0], sc[i][j][1]));
            mhi = fmaxf(mhi, fmaxf(sc[i][j][2], sc[i][j][3]));
        }
        mlo = fmaxf(mlo, __shfl_xor_sync(0xffffffffu, mlo, 1));
        mlo = fmaxf(mlo, __shfl_xor_sync(0xffffffffu, mlo, 2));
        mhi = fmaxf(mhi, __shfl_xor_sync(0xffffffffu, mhi, 1));
        mhi = fmaxf(mhi, __shfl_xor_sync(0xffffffffu, mhi, 2));

        float slo = 0.0f, shi = 0.0f;
        #pragma unroll
        for (int j = 0; j < 7; j++) {
            sc[i][j][0] = __expf(sc[i][j][0] - mlo);
            sc[i][j][1] = __expf(sc[i][j][1] - mlo);
            sc[i][j][2] = __expf(sc[i][j][2] - mhi);
            sc[i][j][3] = __expf(sc[i][j][3] - mhi);
            slo += sc[i][j][0] + sc[i][j][1];
            shi += sc[i][j][2] + sc[i][j][3];
        }
        slo += __shfl_xor_sync(0xffffffffu, slo, 1);
        slo += __shfl_xor_sync(0xffffffffu, slo, 2);
        shi += __shfl_xor_sync(0xffffffffu, shi, 1);
        shi += __shfl_xor_sync(0xffffffffu, shi, 2);
        invlo[i] = 1.0f / slo;
        invhi[i] = 1.0f / shi;
    }

    // ---- PV: O = P V (C->A transform via shuffles; split tf32) ----
    float oacc[4][2][4];
    #pragma unroll
    for (int i = 0; i < 4; i++)
        #pragma unroll
        for (int jn = 0; jn < 2; jn++)
            #pragma unroll
            for (int r = 0; r < 4; r++) oacc[i][jn][r] = 0.0f;

    const unsigned src0 = (lane & 28) | (qcol >> 1);
    const unsigned src1 = src0 + 2;
    const bool odd = (qcol & 1) != 0;

    #pragma unroll
    for (int kt = 0; kt < 7; kt++) {
        uint32_t Bh[2][2], Bl[2][2];
        #pragma unroll
        for (int jn = 0; jn < 2; jn++) {
            const float* bp = vt + (jn * 8 + qrow) * 60 + kt * 8 + qcol;
            float b0 = bp[0], b1 = bp[4];
            float h0 = to_tf32(b0), h1 = to_tf32(b1);
            Bh[jn][0] = __float_as_uint(h0); Bh[jn][1] = __float_as_uint(h1);
            Bl[jn][0] = __float_as_uint(b0 - h0); Bl[jn][1] = __float_as_uint(b1 - h1);
        }
        #pragma unroll
        for (int i = 0; i < 4; i++) {
            float t0 = __shfl_sync(0xffffffffu, sc[i][kt][0], src0);
            float t1 = __shfl_sync(0xffffffffu, sc[i][kt][1], src0);
            float u0 = __shfl_sync(0xffffffffu, sc[i][kt][0], src1);
            float u1 = __shfl_sync(0xffffffffu, sc[i][kt][1], src1);
            float t2 = __shfl_sync(0xffffffffu, sc[i][kt][2], src0);
            float t3 = __shfl_sync(0xffffffffu, sc[i][kt][3], src0);
            float u2 = __shfl_sync(0xffffffffu, sc[i][kt][2], src1);
            float u3 = __shfl_sync(0xffffffffu, sc[i][kt][3], src1);
            float a0 = odd ? t1 : t0;     // P[16i+qrow][8kt+qcol]
            float a1 = odd ? t3 : t2;     // P[16i+qrow+8][8kt+qcol]
            float a2 = odd ? u1 : u0;     // P[16i+qrow][8kt+qcol+4]
            float a3 = odd ? u3 : u2;     // P[16i+qrow+8][8kt+qcol+4]
            float h0 = to_tf32(a0), h1 = to_tf32(a1), h2 = to_tf32(a2), h3 = to_tf32(a3);
            uint32_t Ah0 = __float_as_uint(h0), Ah1 = __float_as_uint(h1);
            uint32_t Ah2 = __float_as_uint(h2), Ah3 = __float_as_uint(h3);
            uint32_t Al0 = __float_as_uint(a0 - h0), Al1 = __float_as_uint(a1 - h1);
            uint32_t Al2 = __float_as_uint(a2 - h2), Al3 = __float_as_uint(a3 - h3);
            #pragma unroll
            for (int jn = 0; jn < 2; jn++) {
                mma_tf32(oacc[i][jn], Ah0, Ah1, Ah2, Ah3, Bh[jn][0], Bh[jn][1]);
                mma_tf32(oacc[i][jn], Ah0, Ah1, Ah2, Ah3, Bl[jn][0], Bl[jn][1]);
                mma_tf32(oacc[i][jn], Al0, Al1, Al2, Al3, Bh[jn][0], Bh[jn][1]);
            }
        }
    }

    // ---- store (predicated rows < 49), 1/rowsum folded here ----
    float* outBase = attnOut + (size_t)g * 49 * 128 + warp * 16;
    #pragma unroll
    for (int i = 0; i < 4; i++) {
        const int rlo = i * 16 + qrow;
        const int rhi = rlo + 8;
        #pragma unroll
        for (int jn = 0; jn < 2; jn++) {
            const int d = jn * 8 + 2 * qcol;
            if (rlo < 49) {
                float2 v;
                v.x = oacc[i][jn][0] * invlo[i];
                v.y = oacc[i][jn][1] * invlo[i];
                *reinterpret_cast<float2*>(outBase + (size_t)rlo * 128 + d) = v;
            }
            if (rhi < 49) {
                float2 v;
                v.x = oacc[i][jn][2] * invhi[i];
                v.y = oacc[i][jn][3] * invhi[i];
                *reinterpret_cast<float2*>(outBase + (size_t)rhi * 128 + d) = v;
            }
        }
    }
}

// ---------------------------------------------------------------------------
// Launch
// ---------------------------------------------------------------------------
extern "C" void kernel_launch(void* const* d_in, const int* in_sizes, int n_in,
                              void* d_out, int out_size)
{
    const float* x       = (const float*)d_in[0];
    const float* ln_g    = (const float*)d_in[1];
    const float* ln_b    = (const float*)d_in[2];
    const float* w_qkv   = (const float*)d_in[3];
    const float* b_qkv   = (const float*)d_in[4];
    const float* w_out   = (const float*)d_in[5];
    const float* b_out   = (const float*)d_in[6];
    float* out           = (float*)d_out;

    void *xw_ptr = nullptr, *qkv_ptr = nullptr, *wT_ptr = nullptr;
    cudaGetSymbolAddress(&xw_ptr, g_xw);
    cudaGetSymbolAddress(&qkv_ptr, g_qkv);
    cudaGetSymbolAddress(&wT_ptr, g_wT);
    float* xw  = (float*)xw_ptr;
    float* qkv = (float*)qkv_ptr;
    float* wT  = (float*)wT_ptr;

    const int smemG = 2 * 128 * SMEM_LDA * sizeof(float);  // 135168 B
    const int smemA = 8 * ATT_WSLAB * sizeof(float);       // 94208 B
    cudaFuncSetAttribute((const void*)gemm_mma_kernel<0, 3>,
                         cudaFuncAttributeMaxDynamicSharedMemorySize, smemG);
    cudaFuncSetAttribute((const void*)gemm_mma_kernel<1, 1>,
                         cudaFuncAttributeMaxDynamicSharedMemorySize, smemG);
    cudaFuncSetAttribute((const void*)attn_mma_kernel,
                         cudaFuncAttributeMaxDynamicSharedMemorySize, smemA);

    // K0: weight transpose (tiny)
    transpose_w_kernel<<<192, 256>>>(w_qkv, w_out, wT);

    // K1: LN + window partition
    ln_partition_kernel<<<NTOK / 8, 256>>>(x, ln_g, ln_b, xw);

    // K2: QKV GEMM tf32 mma  (M=200704, N=384, K=128)
    gemm_mma_kernel<0, 3><<<NTOK / 128, 256, smemG>>>(xw, wT, b_qkv, qkv);

    // K3: tensor-core attention (4096 windows x 8 heads), writes back into xw
    attn_mma_kernel<<<4096, 256, smemA>>>(qkv, xw);

    // K4: out projection tf32 mma + window merge
    gemm_mma_kernel<1, 1><<<NTOK / 128, 256, smemG>>>(xw, wT + 49152, b_out, out);
}

// round 7
// speedup vs baseline: 3.8754x; 1.6109x over previous
#include <cuda_runtime.h>
#include <cstdint>

// ---------------------------------------------------------------------------
// Window-based self-attention (Swin-style), B=64, 56x56, C=128, WS=7, NH=8.
// Round 6: occupancy doubling. attn: 2 warps/head + launch_bounds(256,2).
// GEMM: 64x128 tiles (101KB smem -> 2 CTAs/SM).
// ---------------------------------------------------------------------------

#define NTOK      200704            // 4096 windows * 49 tokens
#define CDIM      128
#define QKV_STRIDE 25690112         // NTOK * CDIM
#define SCALE_ATT 0.25f             // HD^-0.5, HD=16
#define LN_EPS    1e-5f
#define SMEM_LDA  132               // padded row stride (floats) for GEMM

__device__ float g_xw[(size_t)NTOK * CDIM];          // ~102.8 MB (reused for attn out)
__device__ float g_qkv[(size_t)3 * NTOK * CDIM];     // ~308 MB
__device__ float g_wT[384 * 128 + 128 * 128];        // transposed w_qkv | w_out

// ---------------------------------------------------------------------------
// helpers
// ---------------------------------------------------------------------------
__device__ __forceinline__ float to_tf32(float x) {
    asm("cvt.rna.tf32.f32 %0, %0;" : "+f"(x));
    return x;
}
__device__ __forceinline__ void mma_tf32(float* c,
                                         uint32_t a0, uint32_t a1, uint32_t a2, uint32_t a3,
                                         uint32_t b0, uint32_t b1) {
    asm volatile(
        "mma.sync.aligned.m16n8k8.row.col.f32.tf32.tf32.f32 "
        "{%0,%1,%2,%3}, {%4,%5,%6,%7}, {%8,%9}, {%0,%1,%2,%3};"
        : "+f"(c[0]), "+f"(c[1]), "+f"(c[2]), "+f"(c[3])
        : "r"(a0), "r"(a1), "r"(a2), "r"(a3), "r"(b0), "r"(b1));
}

// ---------------------------------------------------------------------------
// K0: transpose weights (w_qkv [128,384] -> [384,128]; w_out [128,128] -> T)
// ---------------------------------------------------------------------------
__global__ void transpose_w_kernel(const float* __restrict__ wqkv,
                                   const float* __restrict__ wout,
                                   float* __restrict__ wT)
{
    const int i = blockIdx.x * 256 + threadIdx.x;
    if (i < 49152) {
        const int k = i / 384, n = i - k * 384;
        wT[n * 128 + k] = wqkv[i];
    }
    if (i < 16384) {
        const int k = i >> 7, n = i & 127;
        wT[49152 + n * 128 + k] = wout[i];
    }
}

// ---------------------------------------------------------------------------
// K1: LayerNorm + window partition. One warp per token.
// ---------------------------------------------------------------------------
__global__ void ln_partition_kernel(const float* __restrict__ x,
                                    const float* __restrict__ gamma,
                                    const float* __restrict__ beta,
                                    float* __restrict__ xw)
{
    const int t    = blockIdx.x * 8 + (threadIdx.x >> 5);
    const int lane = threadIdx.x & 31;

    const int g = t / 49, p = t - g * 49;
    const int b = g >> 6, w = g & 63;
    const int row = (w >> 3) * 7 + p / 7;
    const int col = (w & 7) * 7 + p % 7;

    const size_t src4 = ((size_t)b * 3136 + row * 56 + col) * 32 + lane;
    float4 v = reinterpret_cast<const float4*>(x)[src4];

    float sum = v.x + v.y + v.z + v.w;
    #pragma unroll
    for (int o = 16; o > 0; o >>= 1) sum += __shfl_xor_sync(0xffffffffu, sum, o);
    const float mu = sum * (1.0f / 128.0f);

    float4 d;
    d.x = v.x - mu; d.y = v.y - mu; d.z = v.z - mu; d.w = v.w - mu;
    float sq = d.x * d.x + d.y * d.y + d.z * d.z + d.w * d.w;
    #pragma unroll
    for (int o = 16; o > 0; o >>= 1) sq += __shfl_xor_sync(0xffffffffu, sq, o);
    const float rstd = rsqrtf(sq * (1.0f / 128.0f) + LN_EPS);

    float4 gm = reinterpret_cast<const float4*>(gamma)[lane];
    float4 bt = reinterpret_cast<const float4*>(beta)[lane];
    float4 o;
    o.x = d.x * rstd * gm.x + bt.x;
    o.y = d.y * rstd * gm.y + bt.y;
    o.z = d.z * rstd * gm.z + bt.z;
    o.w = d.w * rstd * gm.w + bt.w;

    reinterpret_cast<float4*>(xw)[(size_t)t * 32 + lane] = o;
}

// ---------------------------------------------------------------------------
// K2/K4: tf32 mma.sync GEMM. 64x128 tile (2 CTAs/SM), K=128 resident,
// 8 warps (2x4), each warp 32x32 = 8 m16n8k8 tiles x 16 k-steps.
// MODE 0 (NBLK=3): QKV (A tile reused over 3 N-blocks; head-scatter out).
// MODE 1 (NBLK=1): out-proj (+bias, window-merge scatter).
// ---------------------------------------------------------------------------
template <int MODE, int NBLK>
__global__ void __launch_bounds__(256, 2)
gemm_mma_kernel(const float* __restrict__ A,
                const float* __restrict__ WT,      // [N_total, 128] row-major
                const float* __restrict__ bias,
                float* __restrict__ out)
{
    extern __shared__ float sm[];
    float* As = sm;                          // [64][SMEM_LDA]
    float* Bs = sm + 64 * SMEM_LDA;          // [128][SMEM_LDA]

    const int tid  = threadIdx.x;
    const int warp = tid >> 5, lane = tid & 31;
    const int wm = (warp >> 2) * 32;         // warp m offset (0/32)
    const int wn = (warp & 3) * 32;          // warp n offset (0/32/64/96)
    const int qrow = lane >> 2;
    const int qcol = lane & 3;
    const int mBase = blockIdx.x * 64;

    const float4* A4 = reinterpret_cast<const float4*>(A);
    #pragma unroll
    for (int i = tid; i < 2048; i += 256) {
        const int m = i >> 5, k4 = i & 31;
        float4 v = A4[(size_t)(mBase + m) * 32 + k4];
        v.x = to_tf32(v.x); v.y = to_tf32(v.y);
        v.z = to_tf32(v.z); v.w = to_tf32(v.w);
        *reinterpret_cast<float4*>(&As[m * SMEM_LDA + k4 * 4]) = v;
    }

    const float* aBase = As + (wm + qrow) * SMEM_LDA + qcol;
    const float* bBase = Bs + (wn + qrow) * SMEM_LDA + qcol;
    const float4* W4 = reinterpret_cast<const float4*>(WT);

    for (int y = 0; y < NBLK; y++) {
        const int nBase = y * 128;

        #pragma unroll
        for (int i = tid; i < 4096; i += 256) {
            const int n = i >> 5, k4 = i & 31;
            float4 v = W4[(size_t)(nBase + n) * 32 + k4];
            v.x = to_tf32(v.x); v.y = to_tf32(v.y);
            v.z = to_tf32(v.z); v.w = to_tf32(v.w);
            *reinterpret_cast<float4*>(&Bs[n * SMEM_LDA + k4 * 4]) = v;
        }
        __syncthreads();

        float acc[2][4][4];
        #pragma unroll
        for (int i = 0; i < 2; i++)
            #pragma unroll
            for (int j = 0; j < 4; j++)
                #pragma unroll
                for (int r = 0; r < 4; r++) acc[i][j][r] = 0.0f;

        #pragma unroll
        for (int ks = 0; ks < 16; ks++) {
            const int kk = ks * 8;
            uint32_t af[2][4];
            #pragma unroll
            for (int i = 0; i < 2; i++) {
                const float* ap = aBase + i * 16 * SMEM_LDA + kk;
                af[i][0] = __float_as_uint(ap[0]);
                af[i][1] = __float_as_uint(ap[8 * SMEM_LDA]);
                af[i][2] = __float_as_uint(ap[4]);
                af[i][3] = __float_as_uint(ap[8 * SMEM_LDA + 4]);
            }
            uint32_t bf[4][2];
            #pragma unroll
            for (int j = 0; j < 4; j++) {
                const float* bp = bBase + j * 8 * SMEM_LDA + kk;
                bf[j][0] = __float_as_uint(bp[0]);
                bf[j][1] = __float_as_uint(bp[4]);
            }
            #pragma unroll
            for (int i = 0; i < 2; i++)
                #pragma unroll
                for (int j = 0; j < 4; j++)
                    mma_tf32(acc[i][j], af[i][0], af[i][1], af[i][2], af[i][3],
                             bf[j][0], bf[j][1]);
        }

        #pragma unroll
        for (int i = 0; i < 2; i++) {
            #pragma unroll
            for (int half = 0; half < 2; half++) {
                const int t = mBase + wm + i * 16 + qrow + half * 8;
                const int g = t / 49, p = t - g * 49;
                if (MODE == 0) {
                    #pragma unroll
                    for (int j = 0; j < 4; j++) {
                        const int jj = nBase + wn + j * 8 + 2 * qcol;
                        const int which = jj >> 7;
                        const int ch = jj & 127;
                        const int h = ch >> 4, d = ch & 15;
                        float2 v;
                        v.x = acc[i][j][half * 2 + 0] + __ldg(&bias[jj]);
                        v.y = acc[i][j][half * 2 + 1] + __ldg(&bias[jj + 1]);
                        *reinterpret_cast<float2*>(
                            out + (size_t)which * QKV_STRIDE +
                            ((size_t)((g * 8 + h) * 49 + p)) * 16 + d) = v;
                    }
                } else {
                    const int b = g >> 6, w = g & 63;
                    const int row = (w >> 3) * 7 + p / 7;
                    const int col = (w & 7) * 7 + p % 7;
                    float* op = out + ((size_t)b * 3136 + row * 56 + col) * 128;
                    #pragma unroll
                    for (int j = 0; j < 4; j++) {
                        const int cofs = wn + j * 8 + 2 * qcol;
                        float2 v;
                        v.x = acc[i][j][half * 2 + 0] + __ldg(&bias[cofs]);
                        v.y = acc[i][j][half * 2 + 1] + __ldg(&bias[cofs + 1]);
                        *reinterpret_cast<float2*>(op + cofs) = v;
                    }
                }
            }
        }
        __syncthreads();
    }
}

// ---------------------------------------------------------------------------
// K3: tensor-core attention, 2 warps per (window, head).
// Block = 8 warps = 4 heads; grid = 8192 (2 blocks per window).
// Warp handles 32 rows (2 m16 tiles): rowhalf 0 -> rows 0..31, 1 -> 32..63.
// Same split-tf32 math as R5 (rel_err preserved); smem slab shared per head.
// ---------------------------------------------------------------------------
#define ATT_WSLAB 2944   // floats per head slab (980 + 980 + 960 + pad)

__global__ void __launch_bounds__(256, 2)
attn_mma_kernel(const float* __restrict__ qkv, float* __restrict__ attnOut)
{
    extern __shared__ float smd[];
    const int g     = blockIdx.x >> 1;            // window
    const int hbase = (blockIdx.x & 1) * 4;       // head group
    const int tid   = threadIdx.x;
    const int hloc  = tid >> 6;                   // 0..3 local head
    const int rowhalf = (tid >> 5) & 1;           // which row half this warp owns
    const int wt    = tid & 63;                   // thread within head pair
    const int lane  = tid & 31;
    const int qrow  = lane >> 2;
    const int qcol  = lane & 3;
    const int head  = hbase + hloc;
    const int wh    = g * 8 + head;

    float* qs  = smd + hloc * ATT_WSLAB;          // [49][20]
    float* ks_ = qs + 980;                        // [49][20]
    float* vt  = qs + 1960;                       // [16][60]  (V transposed)

    const float* qp = qkv + (size_t)wh * 784;
    const float* kp = qp + QKV_STRIDE;
    const float* vp = qp + 2 * (size_t)QKV_STRIDE;

    // zero Vt pad cols 49..59
    for (int i = wt; i < 176; i += 64) {
        const int d = i / 11, c = 49 + (i % 11);
        vt[d * 60 + c] = 0.0f;
    }
    // fill Q (scale folded), K, Vt — 64 threads per head
    for (int idx = wt; idx < 196; idx += 64) {
        const int row = idx >> 2, c4 = (idx & 3) * 4;
        float4 q = reinterpret_cast<const float4*>(qp)[idx];
        q.x *= SCALE_ATT; q.y *= SCALE_ATT; q.z *= SCALE_ATT; q.w *= SCALE_ATT;
        *reinterpret_cast<float4*>(&qs[row * 20 + c4]) = q;
        float4 k = reinterpret_cast<const float4*>(kp)[idx];
        *reinterpret_cast<float4*>(&ks_[row * 20 + c4]) = k;
        float4 v = reinterpret_cast<const float4*>(vp)[idx];
        vt[(c4 + 0) * 60 + row] = v.x;
        vt[(c4 + 1) * 60 + row] = v.y;
        vt[(c4 + 2) * 60 + row] = v.z;
        vt[(c4 + 3) * 60 + row] = v.w;
    }
    __syncthreads();

    // ---- scores: S = Q K^T (split tf32), this warp's 2 row tiles ----
    float sc[2][7][4];
    #pragma unroll
    for (int i = 0; i < 2; i++)
        #pragma unroll
        for (int j = 0; j < 7; j++)
            #pragma unroll
            for (int r = 0; r < 4; r++) sc[i][j][r] = 0.0f;

    #pragma unroll
    for (int ks = 0; ks < 2; ks++) {
        const int kk = ks * 8;
        uint32_t ah[2][4], al[2][4];
        #pragma unroll
        for (int i = 0; i < 2; i++) {
            const int it = rowhalf * 2 + i;
            const float* ap = qs + (it * 16 + qrow) * 20 + kk + qcol;
            float a0 = ap[0], a1 = ap[160], a2 = ap[4], a3 = ap[164];
            float h0 = to_tf32(a0), h1 = to_tf32(a1), h2 = to_tf32(a2), h3 = to_tf32(a3);
            ah[i][0] = __float_as_uint(h0); ah[i][1] = __float_as_uint(h1);
            ah[i][2] = __float_as_uint(h2); ah[i][3] = __float_as_uint(h3);
            al[i][0] = __float_as_uint(a0 - h0); al[i][1] = __float_as_uint(a1 - h1);
            al[i][2] = __float_as_uint(a2 - h2); al[i][3] = __float_as_uint(a3 - h3);
        }
        #pragma unroll
        for (int j = 0; j < 7; j++) {
            const float* bp = ks_ + (j * 8 + qrow) * 20 + kk + qcol;
            float b0 = bp[0], b1 = bp[4];
            float h0 = to_tf32(b0), h1 = to_tf32(b1);
            uint32_t Bh0 = __float_as_uint(h0), Bh1 = __float_as_uint(h1);
            uint32_t Bl0 = __float_as_uint(b0 - h0), Bl1 = __float_as_uint(b1 - h1);
            #pragma unroll
            for (int i = 0; i < 2; i++) {
                mma_tf32(sc[i][j], ah[i][0], ah[i][1], ah[i][2], ah[i][3], Bh0, Bh1);
                mma_tf32(sc[i][j], ah[i][0], ah[i][1], ah[i][2], ah[i][3], Bl0, Bl1);
                mma_tf32(sc[i][j], al[i][0], al[i][1], al[i][2], al[i][3], Bh0, Bh1);
            }
        }
    }

    // ---- softmax in C layout ----
    float invlo[2], invhi[2];
    #pragma unroll
    for (int i = 0; i < 2; i++) {
        if (qcol != 0) { sc[i][6][0] = -1e30f; sc[i][6][2] = -1e30f; }
        sc[i][6][1] = -1e30f; sc[i][6][3] = -1e30f;

        float mlo = -1e30f, mhi = -1e30f;
        #pragma unroll
        for (int j = 0; j < 7; j++) {
            mlo = fmaxf(mlo, fmaxf(sc[i][j][0], sc[i][j][1]));
            mhi = fmaxf(mhi, fmaxf(sc[i][j][2], sc[i][j][3]));
        }
        mlo = fmaxf(mlo, __shfl_xor_sync(0xffffffffu, mlo, 1));
        mlo = fmaxf(mlo, __shfl_xor_sync(0xffffffffu, mlo, 2));
        mhi = fmaxf(mhi, __shfl_xor_sync(0xffffffffu, mhi, 1));
        mhi = fmaxf(mhi, __shfl_xor_sync(0xffffffffu, mhi, 2));

        float slo = 0.0f, shi = 0.0f;
        #pragma unroll
        for (int j = 0; j < 7; j++) {
            sc[i][j][0] = __expf(sc[i][j][0] - mlo);
            sc[i][j][1] = __expf(sc[i][j][1] - mlo);
            sc[i][j][2] = __expf(sc[i][j][2] - mhi);
            sc[i][j][3] = __expf(sc[i][j][3] - mhi);
            slo += sc[i][j][0] + sc[i][j][1];
            shi += sc[i][j][2] + sc[i][j][3];
        }
        slo += __shfl_xor_sync(0xffffffffu, slo, 1);
        slo += __shfl_xor_sync(0xffffffffu, slo, 2);
        shi += __shfl_xor_sync(0xffffffffu, shi, 1);
        shi += __shfl_xor_sync(0xffffffffu, shi, 2);
        invlo[i] = 1.0f / slo;
        invhi[i] = 1.0f / shi;
    }

    // ---- PV: O = P V (C->A via shuffles; split tf32) ----
    float oacc[2][2][4];
    #pragma unroll
    for (int i = 0; i < 2; i++)
        #pragma unroll
        for (int jn = 0; jn < 2; jn++)
            #pragma unroll
            for (int r = 0; r < 4; r++) oacc[i][jn][r] = 0.0f;

    const unsigned src0 = (lane & 28) | (qcol >> 1);
    const unsigned src1 = src0 + 2;
    const bool odd = (qcol & 1) != 0;

    #pragma unroll
    for (int kt = 0; kt < 7; kt++) {
        uint32_t Bh[2][2], Bl[2][2];
        #pragma unroll
        for (int jn = 0; jn < 2; jn++) {
            const float* bp = vt + (jn * 8 + qrow) * 60 + kt * 8 + qcol;
            float b0 = bp[0], b1 = bp[4];
            float h0 = to_tf32(b0), h1 = to_tf32(b1);
            Bh[jn][0] = __float_as_uint(h0); Bh[jn][1] = __float_as_uint(h1);
            Bl[jn][0] = __float_as_uint(b0 - h0); Bl[jn][1] = __float_as_uint(b1 - h1);
        }
        #pragma unroll
        for (int i = 0; i < 2; i++) {
            float t0 = __shfl_sync(0xffffffffu, sc[i][kt][0], src0);
            float t1 = __shfl_sync(0xffffffffu, sc[i][kt][1], src0);
            float u0 = __shfl_sync(0xffffffffu, sc[i][kt][0], src1);
            float u1 = __shfl_sync(0xffffffffu, sc[i][kt][1], src1);
            float t2 = __shfl_sync(0xffffffffu, sc[i][kt][2], src0);
            float t3 = __shfl_sync(0xffffffffu, sc[i][kt][3], src0);
            float u2 = __shfl_sync(0xffffffffu, sc[i][kt][2], src1);
            float u3 = __shfl_sync(0xffffffffu, sc[i][kt][3], src1);
            float a0 = odd ? t1 : t0;
            float a1 = odd ? t3 : t2;
            float a2 = odd ? u1 : u0;
            float a3 = odd ? u3 : u2;
            float h0 = to_tf32(a0), h1 = to_tf32(a1), h2 = to_tf32(a2), h3 = to_tf32(a3);
            uint32_t Ah0 = __float_as_uint(h0), Ah1 = __float_as_uint(h1);
            uint32_t Ah2 = __float_as_uint(h2), Ah3 = __float_as_uint(h3);
            uint32_t Al0 = __float_as_uint(a0 - h0), Al1 = __float_as_uint(a1 - h1);
            uint32_t Al2 = __float_as_uint(a2 - h2), Al3 = __float_as_uint(a3 - h3);
            #pragma unroll
            for (int jn = 0; jn < 2; jn++) {
                mma_tf32(oacc[i][jn], Ah0, Ah1, Ah2, Ah3, Bh[jn][0], Bh[jn][1]);
                mma_tf32(oacc[i][jn], Ah0, Ah1, Ah2, Ah3, Bl[jn][0], Bl[jn][1]);
                mma_tf32(oacc[i][jn], Al0, Al1, Al2, Al3, Bh[jn][0], Bh[jn][1]);
            }
        }
    }

    // ---- store (predicated rows < 49), 1/rowsum folded ----
    float* outBase = attnOut + (size_t)g * 49 * 128 + head * 16;
    #pragma unroll
    for (int i = 0; i < 2; i++) {
        const int it = rowhalf * 2 + i;
        const int rlo = it * 16 + qrow;
        const int rhi = rlo + 8;
        #pragma unroll
        for (int jn = 0; jn < 2; jn++) {
            const int d = jn * 8 + 2 * qcol;
            if (rlo < 49) {
                float2 v;
                v.x = oacc[i][jn][0] * invlo[i];
                v.y = oacc[i][jn][1] * invlo[i];
                *reinterpret_cast<float2*>(outBase + (size_t)rlo * 128 + d) = v;
            }
            if (rhi < 49) {
                float2 v;
                v.x = oacc[i][jn][2] * invhi[i];
                v.y = oacc[i][jn][3] * invhi[i];
                *reinterpret_cast<float2*>(outBase + (size_t)rhi * 128 + d) = v;
            }
        }
    }
}

// ---------------------------------------------------------------------------
// Launch
// ---------------------------------------------------------------------------
extern "C" void kernel_launch(void* const* d_in, const int* in_sizes, int n_in,
                              void* d_out, int out_size)
{
    const float* x       = (const float*)d_in[0];
    const float* ln_g    = (const float*)d_in[1];
    const float* ln_b    = (const float*)d_in[2];
    const float* w_qkv   = (const float*)d_in[3];
    const float* b_qkv   = (const float*)d_in[4];
    const float* w_out   = (const float*)d_in[5];
    const float* b_out   = (const float*)d_in[6];
    float* out           = (float*)d_out;

    void *xw_ptr = nullptr, *qkv_ptr = nullptr, *wT_ptr = nullptr;
    cudaGetSymbolAddress(&xw_ptr, g_xw);
    cudaGetSymbolAddress(&qkv_ptr, g_qkv);
    cudaGetSymbolAddress(&wT_ptr, g_wT);
    float* xw  = (float*)xw_ptr;
    float* qkv = (float*)qkv_ptr;
    float* wT  = (float*)wT_ptr;

    const int smemG = (64 + 128) * SMEM_LDA * sizeof(float);  // 101376 B
    const int smemA = 4 * ATT_WSLAB * sizeof(float);          // 47104 B
    cudaFuncSetAttribute((const void*)gemm_mma_kernel<0, 3>,
                         cudaFuncAttributeMaxDynamicSharedMemorySize, smemG);
    cudaFuncSetAttribute((const void*)gemm_mma_kernel<1, 1>,
                         cudaFuncAttributeMaxDynamicSharedMemorySize, smemG);
    cudaFuncSetAttribute((const void*)attn_mma_kernel,
                         cudaFuncAttributeMaxDynamicSharedMemorySize, smemA);

    // K0: weight transpose (tiny)
    transpose_w_kernel<<<192, 256>>>(w_qkv, w_out, wT);

    // K1: LN + window partition
    ln_partition_kernel<<<NTOK / 8, 256>>>(x, ln_g, ln_b, xw);

    // K2: QKV GEMM tf32 mma  (M=200704, N=384, K=128)
    gemm_mma_kernel<0, 3><<<NTOK / 64, 256, smemG>>>(xw, wT, b_qkv, qkv);

    // K3: tensor-core attention (2 warps/head), writes back into xw
    attn_mma_kernel<<<8192, 256, smemA>>>(qkv, xw);

    // K4: out projection tf32 mma + window merge
    gemm_mma_kernel<1, 1><<<NTOK / 64, 256, smemG>>>(xw, wT + 49152, b_out, out);
}

// round 9
// speedup vs baseline: 4.3835x; 1.1311x over previous
#include <cuda_runtime.h>
#include <cstdint>

// ---------------------------------------------------------------------------
// Window-based self-attention (Swin-style), B=64, 56x56, C=128, WS=7, NH=8.
// Round 7: LN fused into QKV GEMM A-fill (K1 eliminated); attention uses
// single-pass rounded tf32 mma (split removed).
// ---------------------------------------------------------------------------

#define NTOK      200704            // 4096 windows * 49 tokens
#define CDIM      128
#define QKV_STRIDE 25690112         // NTOK * CDIM
#define SCALE_ATT 0.25f             // HD^-0.5, HD=16
#define LN_EPS    1e-5f
#define SMEM_LDA  132               // padded row stride (floats) for GEMM

__device__ float g_xw[(size_t)NTOK * CDIM];          // attn out (K4 input)
__device__ float g_qkv[(size_t)3 * NTOK * CDIM];     // ~308 MB
__device__ float g_wT[384 * 128 + 128 * 128];        // transposed w_qkv | w_out

// ---------------------------------------------------------------------------
// helpers
// ---------------------------------------------------------------------------
__device__ __forceinline__ float to_tf32(float x) {
    asm("cvt.rna.tf32.f32 %0, %0;" : "+f"(x));
    return x;
}
__device__ __forceinline__ void mma_tf32(float* c,
                                         uint32_t a0, uint32_t a1, uint32_t a2, uint32_t a3,
                                         uint32_t b0, uint32_t b1) {
    asm volatile(
        "mma.sync.aligned.m16n8k8.row.col.f32.tf32.tf32.f32 "
        "{%0,%1,%2,%3}, {%4,%5,%6,%7}, {%8,%9}, {%0,%1,%2,%3};"
        : "+f"(c[0]), "+f"(c[1]), "+f"(c[2]), "+f"(c[3])
        : "r"(a0), "r"(a1), "r"(a2), "r"(a3), "r"(b0), "r"(b1));
}

// ---------------------------------------------------------------------------
// K0: transpose weights (w_qkv [128,384] -> [384,128]; w_out [128,128] -> T)
// ---------------------------------------------------------------------------
__global__ void transpose_w_kernel(const float* __restrict__ wqkv,
                                   const float* __restrict__ wout,
                                   float* __restrict__ wT)
{
    const int i = blockIdx.x * 256 + threadIdx.x;
    if (i < 49152) {
        const int k = i / 384, n = i - k * 384;
        wT[n * 128 + k] = wqkv[i];
    }
    if (i < 16384) {
        const int k = i >> 7, n = i & 127;
        wT[49152 + n * 128 + k] = wout[i];
    }
}

// ---------------------------------------------------------------------------
// K2/K4: tf32 mma.sync GEMM. 64x128 tile (2 CTAs/SM), K=128 resident,
// 8 warps (2x4), each warp 32x32, 16 k-steps.
// MODE 0 (NBLK=3): A = raw x; LayerNorm + window-partition fused into A-fill
//                  (each warp iteration holds one full 128-ch row: lane = k4).
//                  QKV epilogue head-scatters into g_qkv.
// MODE 1 (NBLK=1): A = attention output; out-proj epilogue (+bias, merge).
// ---------------------------------------------------------------------------
template <int MODE, int NBLK>
__global__ void __launch_bounds__(256, 2)
gemm_mma_kernel(const float* __restrict__ A,
                const float* __restrict__ WT,      // [N_total, 128] row-major
                const float* __restrict__ bias,
                const float* __restrict__ gamma,   // MODE 0 only
                const float* __restrict__ beta,    // MODE 0 only
                float* __restrict__ out)
{
    extern __shared__ float sm[];
    float* As = sm;                          // [64][SMEM_LDA]
    float* Bs = sm + 64 * SMEM_LDA;          // [128][SMEM_LDA]

    const int tid  = threadIdx.x;
    const int warp = tid >> 5, lane = tid & 31;
    const int wm = (warp >> 2) * 32;         // warp m offset (0/32)
    const int wn = (warp & 3) * 32;          // warp n offset (0/32/64/96)
    const int qrow = lane >> 2;
    const int qcol = lane & 3;
    const int mBase = blockIdx.x * 64;

    // --- A fill: one full row per warp-iteration (lane = k4) ---
    float4 gm, bt;
    if (MODE == 0) {
        gm = reinterpret_cast<const float4*>(gamma)[lane];
        bt = reinterpret_cast<const float4*>(beta)[lane];
    }
    const float4* A4 = reinterpret_cast<const float4*>(A);
    #pragma unroll
    for (int j = 0; j < 8; j++) {
        const int m = warp + 8 * j;          // row in tile
        const int t = mBase + m;             // windowed token index
        float4 v;
        if (MODE == 0) {
            const int g = t / 49, p = t - g * 49;
            const int b = g >> 6, w = g & 63;
            const int row = (w >> 3) * 7 + p / 7;
            const int col = (w & 7) * 7 + p % 7;
            v = A4[((size_t)b * 3136 + row * 56 + col) * 32 + lane];
            // LayerNorm across the warp (full 128-ch row resident)
            float sum = v.x + v.y + v.z + v.w;
            #pragma unroll
            for (int o = 16; o > 0; o >>= 1) sum += __shfl_xor_sync(0xffffffffu, sum, o);
            const float mu = sum * (1.0f / 128.0f);
            float4 d;
            d.x = v.x - mu; d.y = v.y - mu; d.z = v.z - mu; d.w = v.w - mu;
            float sq = d.x * d.x + d.y * d.y + d.z * d.z + d.w * d.w;
            #pragma unroll
            for (int o = 16; o > 0; o >>= 1) sq += __shfl_xor_sync(0xffffffffu, sq, o);
            const float rstd = rsqrtf(sq * (1.0f / 128.0f) + LN_EPS);
            v.x = d.x * rstd * gm.x + bt.x;
            v.y = d.y * rstd * gm.y + bt.y;
            v.z = d.z * rstd * gm.z + bt.z;
            v.w = d.w * rstd * gm.w + bt.w;
        } else {
            v = A4[(size_t)t * 32 + lane];
        }
        v.x = to_tf32(v.x); v.y = to_tf32(v.y);
        v.z = to_tf32(v.z); v.w = to_tf32(v.w);
        *reinterpret_cast<float4*>(&As[m * SMEM_LDA + lane * 4]) = v;
    }

    const float* aBase = As + (wm + qrow) * SMEM_LDA + qcol;
    const float* bBase = Bs + (wn + qrow) * SMEM_LDA + qcol;
    const float4* W4 = reinterpret_cast<const float4*>(WT);

    for (int y = 0; y < NBLK; y++) {
        const int nBase = y * 128;

        #pragma unroll
        for (int i = tid; i < 4096; i += 256) {
            const int n = i >> 5, k4 = i & 31;
            float4 v = W4[(size_t)(nBase + n) * 32 + k4];
            v.x = to_tf32(v.x); v.y = to_tf32(v.y);
            v.z = to_tf32(v.z); v.w = to_tf32(v.w);
            *reinterpret_cast<float4*>(&Bs[n * SMEM_LDA + k4 * 4]) = v;
        }
        __syncthreads();

        float acc[2][4][4];
        #pragma unroll
        for (int i = 0; i < 2; i++)
            #pragma unroll
            for (int j = 0; j < 4; j++)
                #pragma unroll
                for (int r = 0; r < 4; r++) acc[i][j][r] = 0.0f;

        #pragma unroll
        for (int ks = 0; ks < 16; ks++) {
            const int kk = ks * 8;
            uint32_t af[2][4];
            #pragma unroll
            for (int i = 0; i < 2; i++) {
                const float* ap = aBase + i * 16 * SMEM_LDA + kk;
                af[i][0] = __float_as_uint(ap[0]);
                af[i][1] = __float_as_uint(ap[8 * SMEM_LDA]);
                af[i][2] = __float_as_uint(ap[4]);
                af[i][3] = __float_as_uint(ap[8 * SMEM_LDA + 4]);
            }
            uint32_t bf[4][2];
            #pragma unroll
            for (int j = 0; j < 4; j++) {
                const float* bp = bBase + j * 8 * SMEM_LDA + kk;
                bf[j][0] = __float_as_uint(bp[0]);
                bf[j][1] = __float_as_uint(bp[4]);
            }
            #pragma unroll
            for (int i = 0; i < 2; i++)
                #pragma unroll
                for (int j = 0; j < 4; j++)
                    mma_tf32(acc[i][j], af[i][0], af[i][1], af[i][2], af[i][3],
                             bf[j][0], bf[j][1]);
        }

        #pragma unroll
        for (int i = 0; i < 2; i++) {
            #pragma unroll
            for (int half = 0; half < 2; half++) {
                const int t = mBase + wm + i * 16 + qrow + half * 8;
                const int g = t / 49, p = t - g * 49;
                if (MODE == 0) {
                    #pragma unroll
                    for (int j = 0; j < 4; j++) {
                        const int jj = nBase + wn + j * 8 + 2 * qcol;
                        const int which = jj >> 7;
                        const int ch = jj & 127;
                        const int h = ch >> 4, d = ch & 15;
                        float2 v;
                        v.x = acc[i][j][half * 2 + 0] + __ldg(&bias[jj]);
                        v.y = acc[i][j][half * 2 + 1] + __ldg(&bias[jj + 1]);
                        *reinterpret_cast<float2*>(
                            out + (size_t)which * QKV_STRIDE +
                            ((size_t)((g * 8 + h) * 49 + p)) * 16 + d) = v;
                    }
                } else {
                    const int b = g >> 6, w = g & 63;
                    const int row = (w >> 3) * 7 + p / 7;
                    const int col = (w & 7) * 7 + p % 7;
                    float* op = out + ((size_t)b * 3136 + row * 56 + col) * 128;
                    #pragma unroll
                    for (int j = 0; j < 4; j++) {
                        const int cofs = wn + j * 8 + 2 * qcol;
                        float2 v;
                        v.x = acc[i][j][half * 2 + 0] + __ldg(&bias[cofs]);
                        v.y = acc[i][j][half * 2 + 1] + __ldg(&bias[cofs + 1]);
                        *reinterpret_cast<float2*>(op + cofs) = v;
                    }
                }
            }
        }
        __syncthreads();
    }
}

// ---------------------------------------------------------------------------
// K3: tensor-core attention, 2 warps per (window, head), single-pass tf32.
// Block = 8 warps = 4 heads; grid = 8192 (2 blocks per window).
// ---------------------------------------------------------------------------
#define ATT_WSLAB 2944   // floats per head slab (980 + 980 + 960 + pad)

__global__ void __launch_bounds__(256, 2)
attn_mma_kernel(const float* __restrict__ qkv, float* __restrict__ attnOut)
{
    extern __shared__ float smd[];
    const int g     = blockIdx.x >> 1;            // window
    const int hbase = (blockIdx.x & 1) * 4;       // head group
    const int tid   = threadIdx.x;
    const int hloc  = tid >> 6;                   // 0..3 local head
    const int rowhalf = (tid >> 5) & 1;           // warp's row half
    const int wt    = tid & 63;
    const int lane  = tid & 31;
    const int qrow  = lane >> 2;
    const int qcol  = lane & 3;
    const int head  = hbase + hloc;
    const int wh    = g * 8 + head;

    float* qs  = smd + hloc * ATT_WSLAB;          // [49][20]
    float* ks_ = qs + 980;                        // [49][20]
    float* vt  = qs + 1960;                       // [16][60]  (V transposed)

    const float* qp = qkv + (size_t)wh * 784;
    const float* kp = qp + QKV_STRIDE;
    const float* vp = qp + 2 * (size_t)QKV_STRIDE;

    // zero Vt pad cols 49..59
    for (int i = wt; i < 176; i += 64) {
        const int d = i / 11, c = 49 + (i % 11);
        vt[d * 60 + c] = 0.0f;
    }
    // fill Q (scale folded), K, Vt — 64 threads per head
    for (int idx = wt; idx < 196; idx += 64) {
        const int row = idx >> 2, c4 = (idx & 3) * 4;
        float4 q = reinterpret_cast<const float4*>(qp)[idx];
        q.x *= SCALE_ATT; q.y *= SCALE_ATT; q.z *= SCALE_ATT; q.w *= SCALE_ATT;
        *reinterpret_cast<float4*>(&qs[row * 20 + c4]) = q;
        float4 k = reinterpret_cast<const float4*>(kp)[idx];
        *reinterpret_cast<float4*>(&ks_[row * 20 + c4]) = k;
        float4 v = reinterpret_cast<const float4*>(vp)[idx];
        vt[(c4 + 0) * 60 + row] = v.x;
        vt[(c4 + 1) * 60 + row] = v.y;
        vt[(c4 + 2) * 60 + row] = v.z;
        vt[(c4 + 3) * 60 + row] = v.w;
    }
    __syncthreads();

    // ---- scores: S = Q K^T (single-pass rounded tf32) ----
    float sc[2][7][4];
    #pragma unroll
    for (int i = 0; i < 2; i++)
        #pragma unroll
        for (int j = 0; j < 7; j++)
            #pragma unroll
            for (int r = 0; r < 4; r++) sc[i][j][r] = 0.0f;

    #pragma unroll
    for (int ks = 0; ks < 2; ks++) {
        const int kk = ks * 8;
        uint32_t ah[2][4];
        #pragma unroll
        for (int i = 0; i < 2; i++) {
            const int it = rowhalf * 2 + i;
            const float* ap = qs + (it * 16 + qrow) * 20 + kk + qcol;
            ah[i][0] = __float_as_uint(to_tf32(ap[0]));
            ah[i][1] = __float_as_uint(to_tf32(ap[160]));
            ah[i][2] = __float_as_uint(to_tf32(ap[4]));
            ah[i][3] = __float_as_uint(to_tf32(ap[164]));
        }
        #pragma unroll
        for (int j = 0; j < 7; j++) {
            const float* bp = ks_ + (j * 8 + qrow) * 20 + kk + qcol;
            const uint32_t Bh0 = __float_as_uint(to_tf32(bp[0]));
            const uint32_t Bh1 = __float_as_uint(to_tf32(bp[4]));
            #pragma unroll
            for (int i = 0; i < 2; i++)
                mma_tf32(sc[i][j], ah[i][0], ah[i][1], ah[i][2], ah[i][3], Bh0, Bh1);
        }
    }

    // ---- softmax in C layout ----
    float invlo[2], invhi[2];
    #pragma unroll
    for (int i = 0; i < 2; i++) {
        if (qcol != 0) { sc[i][6][0] = -1e30f; sc[i][6][2] = -1e30f; }
        sc[i][6][1] = -1e30f; sc[i][6][3] = -1e30f;

        float mlo = -1e30f, mhi = -1e30f;
        #pragma unroll
        for (int j = 0; j < 7; j++) {
            mlo = fmaxf(mlo, fmaxf(sc[i][j][0], sc[i][j][1]));
            mhi = fmaxf(mhi, fmaxf(sc[i][j][2], sc[i][j][3]));
        }
        mlo = fmaxf(mlo, __shfl_xor_sync(0xffffffffu, mlo, 1));
        mlo = fmaxf(mlo, __shfl_xor_sync(0xffffffffu, mlo, 2));
        mhi = fmaxf(mhi, __shfl_xor_sync(0xffffffffu, mhi, 1));
        mhi = fmaxf(mhi, __shfl_xor_sync(0xffffffffu, mhi, 2));

        float slo = 0.0f, shi = 0.0f;
        #pragma unroll
        for (int j = 0; j < 7; j++) {
            sc[i][j][0] = __expf(sc[i][j][0] - mlo);
            sc[i][j][1] = __expf(sc[i][j][1] - mlo);
            sc[i][j][2] = __expf(sc[i][j][2] - mhi);
            sc[i][j][3] = __expf(sc[i][j][3] - mhi);
            slo += sc[i][j][0] + sc[i][j][1];
            shi += sc[i][j][2] + sc[i][j][3];
        }
        slo += __shfl_xor_sync(0xffffffffu, slo, 1);
        slo += __shfl_xor_sync(0xffffffffu, slo, 2);
        shi += __shfl_xor_sync(0xffffffffu, shi, 1);
        shi += __shfl_xor_sync(0xffffffffu, shi, 2);
        invlo[i] = 1.0f / slo;
        invhi[i] = 1.0f / shi;
    }

    // ---- PV: O = P V (C->A via shuffles; single-pass tf32) ----
    float oacc[2][2][4];
    #pragma unroll
    for (int i = 0; i < 2; i++)
        #pragma unroll
        for (int jn = 0; jn < 2; jn++)
            #pragma unroll
            for (int r = 0; r < 4; r++) oacc[i][jn][r] = 0.0f;

    const unsigned src0 = (lane & 28) | (qcol >> 1);
    const unsigned src1 = src0 + 2;
    const bool odd = (qcol & 1) != 0;

    #pragma unroll
    for (int kt = 0; kt < 7; kt++) {
        uint32_t Bh[2][2];
        #pragma unroll
        for (int jn = 0; jn < 2; jn++) {
            const float* bp = vt + (jn * 8 + qrow) * 60 + kt * 8 + qcol;
            Bh[jn][0] = __float_as_uint(to_tf32(bp[0]));
            Bh[jn][1] = __float_as_uint(to_tf32(bp[4]));
        }
        #pragma unroll
        for (int i = 0; i < 2; i++) {
            float t0 = __shfl_sync(0xffffffffu, sc[i][kt][0], src0);
            float t1 = __shfl_sync(0xffffffffu, sc[i][kt][1], src0);
            float u0 = __shfl_sync(0xffffffffu, sc[i][kt][0], src1);
            float u1 = __shfl_sync(0xffffffffu, sc[i][kt][1], src1);
            float t2 = __shfl_sync(0xffffffffu, sc[i][kt][2], src0);
            float t3 = __shfl_sync(0xffffffffu, sc[i][kt][3], src0);
            float u2 = __shfl_sync(0xffffffffu, sc[i][kt][2], src1);
            float u3 = __shfl_sync(0xffffffffu, sc[i][kt][3], src1);
            const uint32_t Ah0 = __float_as_uint(to_tf32(odd ? t1 : t0));
            const uint32_t Ah1 = __float_as_uint(to_tf32(odd ? t3 : t2));
            const uint32_t Ah2 = __float_as_uint(to_tf32(odd ? u1 : u0));
            const uint32_t Ah3 = __float_as_uint(to_tf32(odd ? u3 : u2));
            #pragma unroll
            for (int jn = 0; jn < 2; jn++)
                mma_tf32(oacc[i][jn], Ah0, Ah1, Ah2, Ah3, Bh[jn][0], Bh[jn][1]);
        }
    }

    // ---- store (predicated rows < 49), 1/rowsum folded ----
    float* outBase = attnOut + (size_t)g * 49 * 128 + head * 16;
    #pragma unroll
    for (int i = 0; i < 2; i++) {
        const int it = rowhalf * 2 + i;
        const int rlo = it * 16 + qrow;
        const int rhi = rlo + 8;
        #pragma unroll
        for (int jn = 0; jn < 2; jn++) {
            const int d = jn * 8 + 2 * qcol;
            if (rlo < 49) {
                float2 v;
                v.x = oacc[i][jn][0] * invlo[i];
                v.y = oacc[i][jn][1] * invlo[i];
                *reinterpret_cast<float2*>(outBase + (size_t)rlo * 128 + d) = v;
            }
            if (rhi < 49) {
                float2 v;
                v.x = oacc[i][jn][2] * invhi[i];
                v.y = oacc[i][jn][3] * invhi[i];
                *reinterpret_cast<float2*>(outBase + (size_t)rhi * 128 + d) = v;
            }
        }
    }
}

// ---------------------------------------------------------------------------
// Launch
// ---------------------------------------------------------------------------
extern "C" void kernel_launch(void* const* d_in, const int* in_sizes, int n_in,
                              void* d_out, int out_size)
{
    const float* x       = (const float*)d_in[0];
    const float* ln_g    = (const float*)d_in[1];
    const float* ln_b    = (const float*)d_in[2];
    const float* w_qkv   = (const float*)d_in[3];
    const float* b_qkv   = (const float*)d_in[4];
    const float* w_out   = (const float*)d_in[5];
    const float* b_out   = (const float*)d_in[6];
    float* out           = (float*)d_out;

    void *xw_ptr = nullptr, *qkv_ptr = nullptr, *wT_ptr = nullptr;
    cudaGetSymbolAddress(&xw_ptr, g_xw);
    cudaGetSymbolAddress(&qkv_ptr, g_qkv);
    cudaGetSymbolAddress(&wT_ptr, g_wT);
    float* xw  = (float*)xw_ptr;
    float* qkv = (float*)qkv_ptr;
    float* wT  = (float*)wT_ptr;

    const int smemG = (64 + 128) * SMEM_LDA * sizeof(float);  // 101376 B
    const int smemA = 4 * ATT_WSLAB * sizeof(float);          // 47104 B
    cudaFuncSetAttribute((const void*)gemm_mma_kernel<0, 3>,
                         cudaFuncAttributeMaxDynamicSharedMemorySize, smemG);
    cudaFuncSetAttribute((const void*)gemm_mma_kernel<1, 1>,
                         cudaFuncAttributeMaxDynamicSharedMemorySize, smemG);
    cudaFuncSetAttribute((const void*)attn_mma_kernel,
                         cudaFuncAttributeMaxDynamicSharedMemorySize, smemA);

    // K0: weight transpose (tiny)
    transpose_w_kernel<<<192, 256>>>(w_qkv, w_out, wT);

    // K2: fused LN + window partition + QKV GEMM (M=200704, N=384, K=128)
    gemm_mma_kernel<0, 3><<<NTOK / 64, 256, smemG>>>(x, wT, b_qkv, ln_g, ln_b, qkv);

    // K3: tensor-core attention (2 warps/head), writes into g_xw
    attn_mma_kernel<<<8192, 256, smemA>>>(qkv, xw);

    // K4: out projection tf32 mma + window merge
    gemm_mma_kernel<1, 1><<<NTOK / 64, 256, smemG>>>(xw, wT + 49152, b_out, nullptr, nullptr, out);
}